// round 3
// baseline (speedup 1.0000x reference)
#include <cuda_runtime.h>
#include <cuda_bf16.h>

// ---------------------------------------------------------------------------
// Problem constants (fixed by the reference)
// ---------------------------------------------------------------------------
#define NB      8
#define LQN     2500
#define DMD     256
#define NHD     8
#define NLV     4
#define NPT     8
#define NZP     4
#define DHD     32
#define LEN_IN  14960
#define MVAL    (NB * LEN_IN)   // 119680  (divisible by 128)
#define MQ      (NB * LQN)      // 20000

// ---------------------------------------------------------------------------
// Scratch (static device globals — no runtime allocation allowed)
// ---------------------------------------------------------------------------
__device__ float g_value[(size_t)MVAL * DMD];  // (N, LEN_IN, NH*DH)
__device__ float g_off[(size_t)MQ * 512];      // (N*LQ, NH*NL*NP*2)
__device__ float g_aw[(size_t)MQ * 256];       // (N*LQ, NH*NL*NP)

// ---------------------------------------------------------------------------
// SGEMM with bias:  C[M,N] = A[M,K] @ B[K,N] + bias[N]
// 128x128 block tile, BK=8, 256 threads, 8x8 per-thread microtile.
// Requires: N % 128 == 0, K % 8 == 0. M guarded.
// ---------------------------------------------------------------------------
__global__ __launch_bounds__(256) void sgemm_bias(
    const float* __restrict__ A, const float* __restrict__ B,
    const float* __restrict__ bias, float* __restrict__ C,
    int M, int N, int K)
{
    __shared__ float As[8 * 128];   // transposed: As[k*128 + m]
    __shared__ float Bs[8 * 128];   // Bs[k*128 + n]

    const int tid = threadIdx.x;
    const int tx = tid & 15;        // 0..15  -> col group
    const int ty = tid >> 4;        // 0..15  -> row group
    const int br = blockIdx.y;
    const int bc = blockIdx.x;

    // A-tile loader mapping: 128 rows x 8 cols, one float4 per thread
    const int rowA = tid >> 1;            // 0..127
    const int colA = (tid & 1) * 4;       // 0 or 4
    // B-tile loader mapping: 8 rows x 128 cols, one float4 per thread
    const int rowB = tid >> 5;            // 0..7
    const int colB = (tid & 31) * 4;      // 0..124

    const int gRowA = br * 128 + rowA;
    const bool aValid = (gRowA < M);
    const float* Aptr = A + (size_t)(aValid ? gRowA : 0) * K + colA;
    const float* Bptr = B + (size_t)rowB * N + (size_t)bc * 128 + colB;

    float acc[8][8];
    #pragma unroll
    for (int i = 0; i < 8; i++)
        #pragma unroll
        for (int j = 0; j < 8; j++) acc[i][j] = 0.f;

    for (int k0 = 0; k0 < K; k0 += 8) {
        float4 a4 = aValid ? *(const float4*)(Aptr + k0) : make_float4(0.f, 0.f, 0.f, 0.f);
        float4 b4 = *(const float4*)(Bptr + (size_t)k0 * N);
        __syncthreads();
        As[(colA + 0) * 128 + rowA] = a4.x;
        As[(colA + 1) * 128 + rowA] = a4.y;
        As[(colA + 2) * 128 + rowA] = a4.z;
        As[(colA + 3) * 128 + rowA] = a4.w;
        *(float4*)&Bs[rowB * 128 + colB] = b4;
        __syncthreads();

        #pragma unroll
        for (int k = 0; k < 8; k++) {
            float4 rm0 = *(const float4*)&As[k * 128 + ty * 8 + 0];
            float4 rm1 = *(const float4*)&As[k * 128 + ty * 8 + 4];
            float4 rn0 = *(const float4*)&Bs[k * 128 + tx * 8 + 0];
            float4 rn1 = *(const float4*)&Bs[k * 128 + tx * 8 + 4];
            float rm[8] = {rm0.x, rm0.y, rm0.z, rm0.w, rm1.x, rm1.y, rm1.z, rm1.w};
            float rn[8] = {rn0.x, rn0.y, rn0.z, rn0.w, rn1.x, rn1.y, rn1.z, rn1.w};
            #pragma unroll
            for (int i = 0; i < 8; i++)
                #pragma unroll
                for (int j = 0; j < 8; j++)
                    acc[i][j] += rm[i] * rn[j];
        }
    }

    const int col0 = bc * 128 + tx * 8;
    float bs[8];
    #pragma unroll
    for (int j = 0; j < 8; j++) bs[j] = bias[col0 + j];

    #pragma unroll
    for (int i = 0; i < 8; i++) {
        int row = br * 128 + ty * 8 + i;
        if (row < M) {
            float4 o0 = make_float4(acc[i][0] + bs[0], acc[i][1] + bs[1],
                                    acc[i][2] + bs[2], acc[i][3] + bs[3]);
            float4 o1 = make_float4(acc[i][4] + bs[4], acc[i][5] + bs[5],
                                    acc[i][6] + bs[6], acc[i][7] + bs[7]);
            *(float4*)&C[(size_t)row * N + col0 + 0] = o0;
            *(float4*)&C[(size_t)row * N + col0 + 4] = o1;
        }
    }
}

// ---------------------------------------------------------------------------
// Fused softmax + deformable bilinear sampling + weighted aggregation.
// One warp per (n, q, h). Lane = point (l*8+p) for scalar prep / softmax,
// then lane = channel d for the gathers. Tap (index, weight) pairs staged in
// SMEM as int2 so the gather loop does 1 broadcast LDS.64 per tap.
// ---------------------------------------------------------------------------
__global__ __launch_bounds__(256) void msda_sample(
    const float* __restrict__ ref,       // (N, LQ, NZ, 2)
    const int*   __restrict__ spatial,   // (NL, 2)
    const int*   __restrict__ lsi,       // (NL,)
    float*       __restrict__ out)       // (N, LQ, DM)
{
    __shared__ int2 sdata[8][32][4];     // [warp][point][tap] = (value row, weight bits)

    const int lane = threadIdx.x & 31;
    const int wid  = threadIdx.x >> 5;
    const int gw   = blockIdx.x * 8 + wid;     // global warp id = (n*LQ+q)*NH + h
    const int h    = gw & 7;
    const int nq   = gw >> 3;                  // n*LQ + q

    // ---- per-point scalar prep (lane = point l*8+p) ----
    const int l = lane >> 3;
    const int p = lane & 7;
    const int hl = spatial[2 * l];
    const int wl = spatial[2 * l + 1];
    const int start = lsi[l];

    const float* offp = g_off + (size_t)nq * 512 + (size_t)(((h * NLV + l) * NPT + p) * 2);
    const float offx = offp[0];
    const float offy = offp[1];

    const int z = p & 3;
    const float* refp = ref + ((size_t)nq * NZP + z) * 2;
    const float locx = refp[0] + offx / (float)wl;
    const float locy = refp[1] + offy / (float)hl;

    const float x = locx * (float)wl - 0.5f;
    const float y = locy * (float)hl - 0.5f;
    const float x0f = floorf(x), y0f = floorf(y);
    const float fx = x - x0f, fy = y - y0f;
    const int x0 = (int)x0f, y0 = (int)y0f;

    // ---- warp softmax over the 32 (l,p) attention logits ----
    float a = g_aw[(size_t)nq * 256 + h * 32 + lane];
    float m = a;
    #pragma unroll
    for (int s = 16; s; s >>= 1) m = fmaxf(m, __shfl_xor_sync(0xffffffffu, m, s));
    float e = __expf(a - m);
    float ssum = e;
    #pragma unroll
    for (int s = 16; s; s >>= 1) ssum += __shfl_xor_sync(0xffffffffu, ssum, s);
    const float awn = e / ssum;

    // ---- 4 bilinear taps: clamp index, zero weight when out of bounds ----
    #pragma unroll
    for (int t = 0; t < 4; t++) {
        const int dx = t & 1, dy = t >> 1;
        const int xi = x0 + dx, yi = y0 + dy;
        const float ww = (dx ? fx : 1.f - fx) * (dy ? fy : 1.f - fy);
        const bool valid = (xi >= 0) && (xi < wl) && (yi >= 0) && (yi < hl);
        const float wv = valid ? ww * awn : 0.f;
        const int xc = min(max(xi, 0), wl - 1);
        const int yc = min(max(yi, 0), hl - 1);
        sdata[wid][lane][t] = make_int2(start + yc * wl + xc, __float_as_int(wv));
    }
    __syncwarp();

    // ---- gather + accumulate (lane = channel d) ----
    const int n = nq / LQN;
    const float* vbase = g_value + (size_t)n * LEN_IN * 256 + h * 32 + lane;
    float acc0 = 0.f, acc1 = 0.f, acc2 = 0.f, acc3 = 0.f;

    #pragma unroll 4
    for (int j = 0; j < 32; j++) {
        const int2 d0 = sdata[wid][j][0];
        const int2 d1 = sdata[wid][j][1];
        const int2 d2 = sdata[wid][j][2];
        const int2 d3 = sdata[wid][j][3];
        acc0 += __int_as_float(d0.y) * vbase[(size_t)d0.x * 256];
        acc1 += __int_as_float(d1.y) * vbase[(size_t)d1.x * 256];
        acc2 += __int_as_float(d2.y) * vbase[(size_t)d2.x * 256];
        acc3 += __int_as_float(d3.y) * vbase[(size_t)d3.x * 256];
    }

    out[(size_t)nq * 256 + h * 32 + lane] = (acc0 + acc1) + (acc2 + acc3);
}

// ---------------------------------------------------------------------------
// Launch
// ---------------------------------------------------------------------------
extern "C" void kernel_launch(void* const* d_in, const int* in_sizes, int n_in,
                              void* d_out, int out_size)
{
    const float* query   = (const float*)d_in[0];
    // d_in[1] = query_pos (unused by the reference forward)
    const float* refpts  = (const float*)d_in[2];
    const float* inflat  = (const float*)d_in[3];
    const int*   spatial = (const int*)d_in[4];
    const int*   lsi     = (const int*)d_in[5];
    const float* Wv      = (const float*)d_in[6];
    const float* bv      = (const float*)d_in[7];
    const float* Wo      = (const float*)d_in[8];
    const float* bo      = (const float*)d_in[9];
    const float* Wa      = (const float*)d_in[10];
    const float* ba      = (const float*)d_in[11];
    float*       out     = (float*)d_out;

    float *pval, *poff, *paw;
    cudaGetSymbolAddress((void**)&pval, g_value);
    cudaGetSymbolAddress((void**)&poff, g_off);
    cudaGetSymbolAddress((void**)&paw,  g_aw);

    // 1) value = input_flatten @ Wv + bv      (119680 x 256 x 256)
    sgemm_bias<<<dim3(DMD / 128, (MVAL + 127) / 128), 256>>>(
        inflat, Wv, bv, pval, MVAL, DMD, DMD);

    // 2) off_raw = query @ Wo + bo            (20000 x 512 x 256)
    sgemm_bias<<<dim3(512 / 128, (MQ + 127) / 128), 256>>>(
        query, Wo, bo, poff, MQ, 512, DMD);

    // 3) aw_raw = query @ Wa + ba             (20000 x 256 x 256)
    sgemm_bias<<<dim3(256 / 128, (MQ + 127) / 128), 256>>>(
        query, Wa, ba, paw, MQ, 256, DMD);

    // 4) softmax + deformable sampling + aggregation
    msda_sample<<<(MQ * NHD) / 8, 256>>>(refpts, spatial, lsi, out);
}

// round 5
// speedup vs baseline: 2.2322x; 2.2322x over previous
#include <cuda_runtime.h>
#include <cstdint>

// ---------------------------------------------------------------------------
// Problem constants
// ---------------------------------------------------------------------------
#define NB      8
#define LQN     2500
#define DMD     256
#define NHD     8
#define NLV     4
#define NPT     8
#define NZP     4
#define LEN_IN  14960
#define MVAL    (NB * LEN_IN)   // 119680 = 935*128
#define MQ      (NB * LQN)      // 20000

// ---------------------------------------------------------------------------
// Scratch (static device globals — no runtime allocation allowed)
// ---------------------------------------------------------------------------
__device__ __align__(256) float g_value[(size_t)MVAL * DMD]; // value GEMM out
__device__ __align__(256) float g_off[(size_t)MQ * 512];     // offsets GEMM out
__device__ __align__(256) float g_aw[(size_t)MQ * 256];      // attn GEMM out

// ---------------------------------------------------------------------------
// PTX helpers (baseline PTX only — no sm_103a-gated instructions)
// ---------------------------------------------------------------------------
__device__ __forceinline__ uint32_t smem_u32(const void* p) {
    uint32_t a;
    asm("{ .reg .u64 t; cvta.to.shared.u64 t, %1; cvt.u32.u64 %0, t; }" : "=r"(a) : "l"(p));
    return a;
}
__device__ __forceinline__ void cp16(void* dst, const void* src, int src_bytes) {
    uint32_t d = smem_u32(dst);
    asm volatile("cp.async.cg.shared.global [%0], [%1], 16, %2;"
                 :: "r"(d), "l"(src), "r"(src_bytes) : "memory");
}
__device__ __forceinline__ void cp_commit() {
    asm volatile("cp.async.commit_group;" ::: "memory");
}
__device__ __forceinline__ void cp_wait1() {
    asm volatile("cp.async.wait_group 1;" ::: "memory");
}
__device__ __forceinline__ void cp_wait0() {
    asm volatile("cp.async.wait_group 0;" ::: "memory");
}
__device__ __forceinline__ uint32_t rna_tf32(float x) {
    uint32_t r; asm("cvt.rna.tf32.f32 %0, %1;" : "=r"(r) : "f"(x)); return r;
}
__device__ __forceinline__ void mma_tf32(float c[4], const uint32_t a[4], const uint32_t b[2]) {
    asm volatile(
        "mma.sync.aligned.m16n8k8.row.col.f32.tf32.tf32.f32 "
        "{%0,%1,%2,%3}, {%4,%5,%6,%7}, {%8,%9}, {%0,%1,%2,%3};"
        : "+f"(c[0]), "+f"(c[1]), "+f"(c[2]), "+f"(c[3])
        : "r"(a[0]), "r"(a[1]), "r"(a[2]), "r"(a[3]), "r"(b[0]), "r"(b[1]));
}

// ---------------------------------------------------------------------------
// TF32 tensor-core GEMM:  C[M,N] = round_tf32(A[M,256]) @ round_tf32(B[256,N]) + bias[N]
//   - B consumed in its native row-major (K,N) layout ('col' mma operand).
//   - CTA tile 128x128, BK=16, 256 threads (8 warps), warp tile 32x64.
//   - Double-buffered cp.async; RNA tf32 rounding applied at fragment load.
// Requires: K == 256, N % 128 == 0. M guarded.
// ---------------------------------------------------------------------------
#define KDIM 256
#define NKT  (KDIM / 16)   // 16 K-tiles

__global__ __launch_bounds__(256) void gemm_tf32mma(
    const float* __restrict__ A, const float* __restrict__ B,
    const float* __restrict__ bias, float* __restrict__ C,
    int M, int N)
{
    __shared__ float As[2][128][20];   // [m][k], stride 20 => conflict-free frags
    __shared__ float Bs[2][16][136];   // [k][n], stride 136 => conflict-free frags

    const int tid  = threadIdx.x;
    const int lane = tid & 31;
    const int wid  = tid >> 5;
    const int gid  = lane >> 2;        // 0..7
    const int tig  = lane & 3;         // 0..3
    const int wm   = (wid >> 1) * 32;  // warp row offset (4 rows of warps)
    const int wn   = (wid & 1) * 64;   // warp col offset (2 cols of warps)
    const int br   = blockIdx.y, bc = blockIdx.x;

    // Loader mappings (2 x 16B chunks per thread per tile)
    const int aRow = tid >> 2, aSeg = tid & 3;    // A: rows aRow, aRow+64
    const int bRow = tid >> 5, bSeg = tid & 31;   // B: rows bRow, bRow+8

    const int gar0 = br * 128 + aRow;
    const int gar1 = gar0 + 64;
    const float* aSrc = A + (size_t)(gar0 < M ? gar0 : 0) * KDIM + aSeg * 4;
    const float* aSrc1 = A + (size_t)(gar1 < M ? gar1 : 0) * KDIM + aSeg * 4;
    const int av0 = (gar0 < M) ? 16 : 0;
    const int av1 = (gar1 < M) ? 16 : 0;
    const float* bSrc = B + (size_t)bRow * N + bc * 128 + bSeg * 4;

    float c[2][8][4];
    #pragma unroll
    for (int mi = 0; mi < 2; mi++)
        #pragma unroll
        for (int nj = 0; nj < 8; nj++)
            #pragma unroll
            for (int q = 0; q < 4; q++) c[mi][nj][q] = 0.f;

    // ---- stage loader ----
    auto load_stage = [&](int kt, int buf) {
        const int k0 = kt * 16;
        cp16(&As[buf][aRow][aSeg * 4],      aSrc  + k0, av0);
        cp16(&As[buf][aRow + 64][aSeg * 4], aSrc1 + k0, av1);
        cp16(&Bs[buf][bRow][bSeg * 4],      bSrc + (size_t)k0 * N, 16);
        cp16(&Bs[buf][bRow + 8][bSeg * 4],  bSrc + (size_t)(k0 + 8) * N, 16);
        cp_commit();
    };

    load_stage(0, 0);

    for (int kt = 0; kt < NKT; kt++) {
        const int buf = kt & 1;
        if (kt + 1 < NKT) {
            load_stage(kt + 1, buf ^ 1);
            cp_wait1();
        } else {
            cp_wait0();
        }
        __syncthreads();

        #pragma unroll
        for (int ks = 0; ks < 16; ks += 8) {
            uint32_t a[2][4], b[8][2];
            #pragma unroll
            for (int mi = 0; mi < 2; mi++) {
                const int m0 = wm + mi * 16 + gid;
                a[mi][0] = rna_tf32(As[buf][m0][ks + tig]);
                a[mi][1] = rna_tf32(As[buf][m0 + 8][ks + tig]);
                a[mi][2] = rna_tf32(As[buf][m0][ks + tig + 4]);
                a[mi][3] = rna_tf32(As[buf][m0 + 8][ks + tig + 4]);
            }
            #pragma unroll
            for (int nj = 0; nj < 8; nj++) {
                const int n0 = wn + nj * 8 + gid;
                b[nj][0] = rna_tf32(Bs[buf][ks + tig][n0]);
                b[nj][1] = rna_tf32(Bs[buf][ks + tig + 4][n0]);
            }
            #pragma unroll
            for (int mi = 0; mi < 2; mi++)
                #pragma unroll
                for (int nj = 0; nj < 8; nj++)
                    mma_tf32(c[mi][nj], a[mi], b[nj]);
        }
        __syncthreads();
    }

    // ---- epilogue: bias + store (float2 per fragment half) ----
    #pragma unroll
    for (int mi = 0; mi < 2; mi++) {
        const int r0 = br * 128 + wm + mi * 16 + gid;
        #pragma unroll
        for (int nj = 0; nj < 8; nj++) {
            const int col = bc * 128 + wn + nj * 8 + tig * 2;
            const float2 bb = *(const float2*)(bias + col);
            if (r0 < M) {
                float2 o = make_float2(c[mi][nj][0] + bb.x, c[mi][nj][1] + bb.y);
                *(float2*)(C + (size_t)r0 * N + col) = o;
            }
            if (r0 + 8 < M) {
                float2 o = make_float2(c[mi][nj][2] + bb.x, c[mi][nj][3] + bb.y);
                *(float2*)(C + (size_t)(r0 + 8) * N + col) = o;
            }
        }
    }
}

// ---------------------------------------------------------------------------
// Fused softmax + deformable bilinear sampling + aggregation.
// One warp per (n, q, h). Phase 1: lane = point (softmax + tap prep -> SMEM).
// Phase 2: lane = (tap, channel-group): 1 LDS.64 + 1 LDG.128 + 4 FFMA per
// point, then shfl-xor reduction across the 4 tap groups.
// ---------------------------------------------------------------------------
__global__ __launch_bounds__(256) void msda_sample(
    const float* __restrict__ ref,       // (N, LQ, NZ, 2)
    const int*   __restrict__ spatial,   // (NL, 2)
    const int*   __restrict__ lsi,       // (NL,)
    float*       __restrict__ out)       // (N, LQ, DM)
{
    __shared__ int2 sdata[8][32][4];     // [warp][point][tap] = (row, weight bits)

    const int lane = threadIdx.x & 31;
    const int wid  = threadIdx.x >> 5;
    const int gw   = blockIdx.x * 8 + wid;
    const int h    = gw & 7;
    const int nq   = gw >> 3;

    // ---- per-point prep (lane = point l*8+p) ----
    const int l = lane >> 3;
    const int p = lane & 7;
    const int hl = spatial[2 * l];
    const int wl = spatial[2 * l + 1];
    const int start = lsi[l];

    const float* offp = g_off + (size_t)nq * 512 + (size_t)(((h * NLV + l) * NPT + p) * 2);
    const float offx = offp[0];
    const float offy = offp[1];
    const int z = p & 3;
    const float* refp = ref + ((size_t)nq * NZP + z) * 2;
    const float locx = refp[0] + offx / (float)wl;
    const float locy = refp[1] + offy / (float)hl;
    const float x = locx * (float)wl - 0.5f;
    const float y = locy * (float)hl - 0.5f;
    const float x0f = floorf(x), y0f = floorf(y);
    const float fx = x - x0f, fy = y - y0f;
    const int x0 = (int)x0f, y0 = (int)y0f;

    // warp softmax over 32 logits
    float a = g_aw[(size_t)nq * 256 + h * 32 + lane];
    float m = a;
    #pragma unroll
    for (int s = 16; s; s >>= 1) m = fmaxf(m, __shfl_xor_sync(0xffffffffu, m, s));
    float e = __expf(a - m);
    float ssum = e;
    #pragma unroll
    for (int s = 16; s; s >>= 1) ssum += __shfl_xor_sync(0xffffffffu, ssum, s);
    const float awn = e / ssum;

    #pragma unroll
    for (int t = 0; t < 4; t++) {
        const int dx = t & 1, dy = t >> 1;
        const int xi = x0 + dx, yi = y0 + dy;
        const float ww = (dx ? fx : 1.f - fx) * (dy ? fy : 1.f - fy);
        const bool valid = (xi >= 0) && (xi < wl) && (yi >= 0) && (yi < hl);
        const float wv = valid ? ww * awn : 0.f;
        const int xc = min(max(xi, 0), wl - 1);
        const int yc = min(max(yi, 0), hl - 1);
        sdata[wid][lane][t] = make_int2(start + yc * wl + xc, __float_as_int(wv));
    }
    __syncwarp();

    // ---- gather: lane = tap t2 (lane>>3) x channel group cg (lane&7) ----
    const int n  = nq / LQN;
    const int t2 = lane >> 3;
    const int cg = lane & 7;
    const float4* vbase = (const float4*)(g_value + (size_t)n * LEN_IN * 256 + h * 32) + cg;
    float4 acc = make_float4(0.f, 0.f, 0.f, 0.f);

    #pragma unroll 4
    for (int j = 0; j < 32; j++) {
        const int2 d = sdata[wid][j][t2];
        const float w = __int_as_float(d.y);
        const float4 v = vbase[(size_t)d.x * 64];
        acc.x += w * v.x; acc.y += w * v.y; acc.z += w * v.z; acc.w += w * v.w;
    }

    // reduce across the 4 tap groups (xor 8, 16)
    #pragma unroll
    for (int s = 8; s <= 16; s <<= 1) {
        acc.x += __shfl_xor_sync(0xffffffffu, acc.x, s);
        acc.y += __shfl_xor_sync(0xffffffffu, acc.y, s);
        acc.z += __shfl_xor_sync(0xffffffffu, acc.z, s);
        acc.w += __shfl_xor_sync(0xffffffffu, acc.w, s);
    }
    if (t2 == 0)
        ((float4*)(out + (size_t)nq * 256 + h * 32))[cg] = acc;
}

// ---------------------------------------------------------------------------
// Launch
// ---------------------------------------------------------------------------
extern "C" void kernel_launch(void* const* d_in, const int* in_sizes, int n_in,
                              void* d_out, int out_size)
{
    const float* query   = (const float*)d_in[0];
    // d_in[1] = query_pos (unused by the reference forward)
    const float* refpts  = (const float*)d_in[2];
    const float* inflat  = (const float*)d_in[3];
    const int*   spatial = (const int*)d_in[4];
    const int*   lsi     = (const int*)d_in[5];
    const float* Wv      = (const float*)d_in[6];
    const float* bv      = (const float*)d_in[7];
    const float* Wo      = (const float*)d_in[8];
    const float* bo      = (const float*)d_in[9];
    const float* Wa      = (const float*)d_in[10];
    const float* ba      = (const float*)d_in[11];
    float*       out     = (float*)d_out;

    float *pval, *poff, *paw;
    cudaGetSymbolAddress((void**)&pval, g_value);
    cudaGetSymbolAddress((void**)&poff, g_off);
    cudaGetSymbolAddress((void**)&paw,  g_aw);

    // 1) value = input_flatten @ Wv + bv    (119680 x 256 x 256)
    gemm_tf32mma<<<dim3(2, MVAL / 128), 256>>>(inflat, Wv, bv, pval, MVAL, 256);
    // 2) off   = query @ Wo + bo            (20000 x 512 x 256)
    gemm_tf32mma<<<dim3(4, (MQ + 127) / 128), 256>>>(query, Wo, bo, poff, MQ, 512);
    // 3) aw    = query @ Wa + ba            (20000 x 256 x 256)
    gemm_tf32mma<<<dim3(2, (MQ + 127) / 128), 256>>>(query, Wa, ba, paw, MQ, 256);

    // 4) softmax + deformable sampling + aggregation
    msda_sample<<<(MQ * NHD) / 8, 256>>>(refpts, spatial, lsi, out);
}

// round 6
// speedup vs baseline: 2.9921x; 1.3404x over previous
#include <cuda_runtime.h>
#include <cuda_fp16.h>
#include <cstdint>

// ---------------------------------------------------------------------------
// Problem constants
// ---------------------------------------------------------------------------
#define NB      8
#define LQN     2500
#define NHD     8
#define NLV     4
#define NPT     8
#define NZP     4
#define LEN_IN  14960
#define MVAL    (NB * LEN_IN)   // 119680 = 935*128
#define MQ      (NB * LQN)      // 20000

// ---------------------------------------------------------------------------
// Scratch (static device globals)
// ---------------------------------------------------------------------------
__device__ __align__(256) __half g_ah[(size_t)MVAL * 256];   // fp16 input_flatten
__device__ __align__(256) __half g_qh[(size_t)MQ * 256];     // fp16 query
__device__ __align__(256) __half g_WvT[256 * 256];           // [n][k] fp16
__device__ __align__(256) __half g_WqT[768 * 256];           // Wo|Wa fused, [n][k] fp16
__device__ __align__(256) float  g_bq[768];                  // bo|ba fused
__device__ __align__(256) __half g_valueh[(size_t)MVAL * 256]; // head-major (n,h,token,32)
__device__ __align__(256) float  g_qout[(size_t)MQ * 768];   // cols 0-511 off, 512-767 aw

// ---------------------------------------------------------------------------
// PTX helpers (baseline PTX only)
// ---------------------------------------------------------------------------
__device__ __forceinline__ uint32_t smem_u32(const void* p) {
    uint32_t a;
    asm("{ .reg .u64 t; cvta.to.shared.u64 t, %1; cvt.u32.u64 %0, t; }" : "=r"(a) : "l"(p));
    return a;
}
__device__ __forceinline__ void cp16(uint32_t dst, const void* src, int src_bytes) {
    asm volatile("cp.async.cg.shared.global [%0], [%1], 16, %2;"
                 :: "r"(dst), "l"(src), "r"(src_bytes) : "memory");
}
__device__ __forceinline__ void cp_commit() { asm volatile("cp.async.commit_group;" ::: "memory"); }
__device__ __forceinline__ void cp_wait1()  { asm volatile("cp.async.wait_group 1;" ::: "memory"); }
__device__ __forceinline__ void cp_wait0()  { asm volatile("cp.async.wait_group 0;" ::: "memory"); }

__device__ __forceinline__ void ldm_x4(uint32_t r[4], uint32_t addr) {
    asm volatile("ldmatrix.sync.aligned.m8n8.x4.shared.b16 {%0,%1,%2,%3}, [%4];"
                 : "=r"(r[0]), "=r"(r[1]), "=r"(r[2]), "=r"(r[3]) : "r"(addr));
}
__device__ __forceinline__ void mma16816(float c[4], const uint32_t a[4], const uint32_t b[2]) {
    asm volatile(
        "mma.sync.aligned.m16n8k16.row.col.f32.f16.f16.f32 "
        "{%0,%1,%2,%3}, {%4,%5,%6,%7}, {%8,%9}, {%0,%1,%2,%3};"
        : "+f"(c[0]), "+f"(c[1]), "+f"(c[2]), "+f"(c[3])
        : "r"(a[0]), "r"(a[1]), "r"(a[2]), "r"(a[3]), "r"(b[0]), "r"(b[1]));
}

// ---------------------------------------------------------------------------
// Prepass kernels
// ---------------------------------------------------------------------------
__global__ void f2h(const float4* __restrict__ in, uint2* __restrict__ out, int n4) {
    int stride = gridDim.x * blockDim.x;
    for (int i = blockIdx.x * blockDim.x + threadIdx.x; i < n4; i += stride) {
        float4 v = in[i];
        __half2 a = __floats2half2_rn(v.x, v.y);
        __half2 b = __floats2half2_rn(v.z, v.w);
        out[i] = make_uint2(*(const uint32_t*)&a, *(const uint32_t*)&b);
    }
}
// Wv (256,256) -> WvT[n][k] fp16
__global__ void wvt(const float* __restrict__ W, __half* __restrict__ WT) {
    int idx = blockIdx.x * blockDim.x + threadIdx.x;
    if (idx < 256 * 256) {
        int n = idx >> 8, k = idx & 255;
        WT[idx] = __float2half(W[k * 256 + n]);
    }
}
// Wo (256,512) + Wa (256,256) -> WqT[768][256] fp16
__global__ void wqt(const float* __restrict__ Wo, const float* __restrict__ Wa,
                    __half* __restrict__ WT) {
    int idx = blockIdx.x * blockDim.x + threadIdx.x;
    if (idx < 768 * 256) {
        int n = idx >> 8, k = idx & 255;
        float v = (n < 512) ? Wo[k * 512 + n] : Wa[k * 256 + (n - 512)];
        WT[idx] = __float2half(v);
    }
}
__global__ void bcat(const float* __restrict__ bo, const float* __restrict__ ba,
                     float* __restrict__ bq) {
    int t = blockIdx.x * blockDim.x + threadIdx.x;
    if (t < 768) bq[t] = (t < 512) ? bo[t] : ba[t - 512];
}

// ---------------------------------------------------------------------------
// FP16 tensor-core GEMM:  C[M,N] = A[M,256] @ BT[N,256]^T + bias[N]
// CTA 128x128, BK=32, 8 warps (warp tile 32x64), double-buffered cp.async,
// ldmatrix fragments, 80-byte padded SMEM rows (bank-conflict-free).
// VOUT=true: write fp16 head-major value tensor; else fp32 row-major (ldc=N).
// ---------------------------------------------------------------------------
#define ROWB 80                      // bytes per 32-half SMEM row
#define TILEB (128 * ROWB)           // 10240
#define BUFB  (2 * TILEB)            // A+B per stage

template<bool VOUT>
__global__ __launch_bounds__(256) void gemm_f16(
    const __half* __restrict__ A, const __half* __restrict__ BT,
    const float* __restrict__ bias, float* __restrict__ Cf, __half* __restrict__ Ch,
    int M, int N)
{
    __shared__ __align__(16) unsigned char sm[2 * BUFB];
    const uint32_t smb = smem_u32(sm);

    const int tid = threadIdx.x;
    const int lane = tid & 31, wid = tid >> 5;
    const int gid = lane >> 2, tig = lane & 3;
    const int wm = (wid >> 1) * 32, wn = (wid & 1) * 64;
    const int br = blockIdx.y, bc = blockIdx.x;

    // loader: thread -> chunks (r0,k0) and (r0+64,k0); chunk = 16B = 8 halves
    const int r0 = tid >> 2, k0 = tid & 3;
    const int gr0 = br * 128 + r0, gr1 = gr0 + 64;
    const __half* aP0 = A + (size_t)(gr0 < M ? gr0 : 0) * 256 + k0 * 8;
    const __half* aP1 = A + (size_t)(gr1 < M ? gr1 : 0) * 256 + k0 * 8;
    const int av0 = (gr0 < M) ? 16 : 0, av1 = (gr1 < M) ? 16 : 0;
    const __half* bP0 = BT + (size_t)(bc * 128 + r0) * 256 + k0 * 8;
    const __half* bP1 = BT + (size_t)(bc * 128 + r0 + 64) * 256 + k0 * 8;
    const uint32_t offA0 = r0 * ROWB + k0 * 16;
    const uint32_t offA1 = (r0 + 64) * ROWB + k0 * 16;

    float c[2][8][4];
    #pragma unroll
    for (int mi = 0; mi < 2; mi++)
        #pragma unroll
        for (int nj = 0; nj < 8; nj++)
            #pragma unroll
            for (int q = 0; q < 4; q++) c[mi][nj][q] = 0.f;

    auto load_stage = [&](int kt, int buf) {
        const uint32_t as = smb + buf * BUFB;
        const uint32_t bs = as + TILEB;
        cp16(as + offA0, aP0 + kt * 32, av0);
        cp16(as + offA1, aP1 + kt * 32, av1);
        cp16(bs + offA0, bP0 + kt * 32, 16);
        cp16(bs + offA1, bP1 + kt * 32, 16);
        cp_commit();
    };

    load_stage(0, 0);

    #pragma unroll 1
    for (int kt = 0; kt < 8; kt++) {
        const int buf = kt & 1;
        if (kt < 7) { load_stage(kt + 1, buf ^ 1); cp_wait1(); }
        else        { cp_wait0(); }
        __syncthreads();

        const uint32_t asB = smb + buf * BUFB;
        const uint32_t bsB = asB + TILEB;

        #pragma unroll
        for (int ks = 0; ks < 32; ks += 16) {
            const int kc0 = ks >> 3;
            uint32_t a[2][4], b[8][2];
            #pragma unroll
            for (int mi = 0; mi < 2; mi++) {
                const int row = wm + mi * 16 + (lane & 15);
                ldm_x4(a[mi], asB + row * ROWB + (kc0 + (lane >> 4)) * 16);
            }
            #pragma unroll
            for (int njp = 0; njp < 4; njp++) {
                const int row = wn + njp * 16 + ((lane >> 4) << 3) + (lane & 7);
                uint32_t t[4];
                ldm_x4(t, bsB + row * ROWB + (kc0 + ((lane >> 3) & 1)) * 16);
                b[2 * njp][0] = t[0]; b[2 * njp][1] = t[1];
                b[2 * njp + 1][0] = t[2]; b[2 * njp + 1][1] = t[3];
            }
            #pragma unroll
            for (int mi = 0; mi < 2; mi++)
                #pragma unroll
                for (int nj = 0; nj < 8; nj++)
                    mma16816(c[mi][nj], a[mi], b[nj]);
        }
        __syncthreads();
    }

    // ---- epilogue ----
    #pragma unroll
    for (int mi = 0; mi < 2; mi++) {
        const int rbase = br * 128 + wm + mi * 16 + gid;
        #pragma unroll
        for (int hh = 0; hh < 2; hh++) {
            const int row = rbase + hh * 8;
            if (row >= M) continue;
            if (VOUT) {
                const int n = row / LEN_IN, tok = row - n * LEN_IN;
                #pragma unroll
                for (int nj = 0; nj < 8; nj++) {
                    const int col = bc * 128 + wn + nj * 8 + tig * 2;
                    const float2 bb = *(const float2*)(bias + col);
                    __half2 hv = __floats2half2_rn(c[mi][nj][2 * hh] + bb.x,
                                                   c[mi][nj][2 * hh + 1] + bb.y);
                    const int h = col >> 5, ch = col & 31;
                    *(__half2*)(Ch + (((size_t)(n * 8 + h) * LEN_IN + tok) * 32 + ch)) = hv;
                }
            } else {
                #pragma unroll
                for (int nj = 0; nj < 8; nj++) {
                    const int col = bc * 128 + wn + nj * 8 + tig * 2;
                    const float2 bb = *(const float2*)(bias + col);
                    float2 o = make_float2(c[mi][nj][2 * hh] + bb.x,
                                           c[mi][nj][2 * hh + 1] + bb.y);
                    *(float2*)(Cf + (size_t)row * N + col) = o;
                }
            }
        }
    }
}

// ---------------------------------------------------------------------------
// Fused softmax + deformable bilinear sampling + aggregation (fp16 value,
// head-major layout). One warp per (n,q,h).
// Phase 1 (lane = point): softmax + per-point tap prep -> sdata[point][row]
//   = int4{ token_base, w_slot0, w_slot1, 0 } (weights include awn + clamping).
// Phase 2 (lane = p1|ry|s|cg): 2 points/iter; each lane loads 8 fp16 channels
//   of one (point,row,col-slot); shfl-xor reduction over (p1,ry,s).
// ---------------------------------------------------------------------------
__global__ __launch_bounds__(256) void msda_sample(
    const float* __restrict__ ref,       // (N, LQ, NZ, 2)
    const int*   __restrict__ spatial,   // (NL, 2)
    const int*   __restrict__ lsi,       // (NL,)
    float*       __restrict__ out)       // (N, LQ, 256)
{
    __shared__ int4 sdata[8][32][2];

    const int lane = threadIdx.x & 31;
    const int wid  = threadIdx.x >> 5;
    const int gw   = blockIdx.x * 8 + wid;
    const int h    = gw & 7;
    const int nq   = gw >> 3;

    // ---- phase 1: lane = point (l*8+p) ----
    {
        const int l = lane >> 3, p = lane & 7;
        const int hl = spatial[2 * l], wl = spatial[2 * l + 1];
        const int start = lsi[l];

        const float2 offv = *(const float2*)(g_qout + (size_t)nq * 768 + (h * 4 + l) * 16 + p * 2);
        const int z = p & 3;
        const float2 rp = *(const float2*)(ref + ((size_t)nq * NZP + z) * 2);
        const float x = (rp.x + offv.x / (float)wl) * (float)wl - 0.5f;
        const float y = (rp.y + offv.y / (float)hl) * (float)hl - 0.5f;
        const float x0f = floorf(x), y0f = floorf(y);
        const float fx = x - x0f, fy = y - y0f;
        const int x0 = (int)x0f, y0 = (int)y0f;

        // warp softmax
        float a = g_qout[(size_t)nq * 768 + 512 + h * 32 + lane];
        float m = a;
        #pragma unroll
        for (int s = 16; s; s >>= 1) m = fmaxf(m, __shfl_xor_sync(0xffffffffu, m, s));
        float e = __expf(a - m);
        float ssum = e;
        #pragma unroll
        for (int s = 16; s; s >>= 1) ssum += __shfl_xor_sync(0xffffffffu, ssum, s);
        const float awn = e / ssum;

        const int bx = min(max(x0, 0), wl - 2);
        const int u0 = bx - x0;          // slot0 dx relative to x0
        const float wx0 = (u0 == 0) ? (1.f - fx) : ((u0 == 1) ? fx : 0.f);
        const float wx1 = (u0 + 1 == 0) ? (1.f - fx) : ((u0 + 1 == 1) ? fx : 0.f);

        #pragma unroll
        for (int ry = 0; ry < 2; ry++) {
            const int yi = y0 + ry;
            const bool vy = (yi >= 0) && (yi < hl);
            const int yc = min(max(yi, 0), hl - 1);
            const float wy = (ry ? fy : 1.f - fy) * (vy ? awn : 0.f);
            sdata[wid][lane][ry] = make_int4(start + yc * wl + bx,
                                             __float_as_int(wx0 * wy),
                                             __float_as_int(wx1 * wy), 0);
        }
    }
    __syncwarp();

    // ---- phase 2 ----
    const int n  = nq / LQN;
    const int p1 = lane >> 4;            // point parity
    const int ry = (lane >> 3) & 1;      // row slot
    const int s  = (lane >> 2) & 1;      // col slot
    const int cg = lane & 3;             // 8-channel chunk
    const __half* vplane = g_valueh + ((size_t)(n * 8 + h)) * LEN_IN * 32;

    float acc[8];
    #pragma unroll
    for (int i = 0; i < 8; i++) acc[i] = 0.f;

    #pragma unroll 4
    for (int j = 0; j < 16; j++) {
        const int pt = 2 * j + p1;
        const int4 sd = sdata[wid][pt][ry];
        const float w = __int_as_float(s ? sd.z : sd.y);
        const uint4 v = *((const uint4*)(vplane + ((size_t)(sd.x + s) << 5)) + cg);
        const float2 f0 = __half22float2(*(const __half2*)&v.x);
        const float2 f1 = __half22float2(*(const __half2*)&v.y);
        const float2 f2 = __half22float2(*(const __half2*)&v.z);
        const float2 f3 = __half22float2(*(const __half2*)&v.w);
        acc[0] += w * f0.x; acc[1] += w * f0.y;
        acc[2] += w * f1.x; acc[3] += w * f1.y;
        acc[4] += w * f2.x; acc[5] += w * f2.y;
        acc[6] += w * f3.x; acc[7] += w * f3.y;
    }

    // reduce over (p1, ry, s)
    #pragma unroll
    for (int st = 16; st >= 4; st >>= 1) {
        #pragma unroll
        for (int i = 0; i < 8; i++)
            acc[i] += __shfl_xor_sync(0xffffffffu, acc[i], st);
    }
    if (lane < 4) {
        float* base = out + (size_t)nq * 256 + h * 32 + lane * 8;
        *(float4*)base       = make_float4(acc[0], acc[1], acc[2], acc[3]);
        *(float4*)(base + 4) = make_float4(acc[4], acc[5], acc[6], acc[7]);
    }
}

// ---------------------------------------------------------------------------
// Launch
// ---------------------------------------------------------------------------
extern "C" void kernel_launch(void* const* d_in, const int* in_sizes, int n_in,
                              void* d_out, int out_size)
{
    const float* query   = (const float*)d_in[0];
    // d_in[1] = query_pos (unused by the reference forward)
    const float* refpts  = (const float*)d_in[2];
    const float* inflat  = (const float*)d_in[3];
    const int*   spatial = (const int*)d_in[4];
    const int*   lsi     = (const int*)d_in[5];
    const float* Wv      = (const float*)d_in[6];
    const float* bv      = (const float*)d_in[7];
    const float* Wo      = (const float*)d_in[8];
    const float* bo      = (const float*)d_in[9];
    const float* Wa      = (const float*)d_in[10];
    const float* ba      = (const float*)d_in[11];
    float*       out     = (float*)d_out;

    __half *pah, *pqh, *pWvT, *pWqT, *pvalh;
    float *pbq, *pqout;
    cudaGetSymbolAddress((void**)&pah,   g_ah);
    cudaGetSymbolAddress((void**)&pqh,   g_qh);
    cudaGetSymbolAddress((void**)&pWvT,  g_WvT);
    cudaGetSymbolAddress((void**)&pWqT,  g_WqT);
    cudaGetSymbolAddress((void**)&pbq,   g_bq);
    cudaGetSymbolAddress((void**)&pvalh, g_valueh);
    cudaGetSymbolAddress((void**)&pqout, g_qout);

    // 0) fp16 conversions / weight transposes / bias concat
    f2h<<<4096, 256>>>((const float4*)inflat, (uint2*)pah, MVAL * 256 / 4);
    f2h<<<2048, 256>>>((const float4*)query,  (uint2*)pqh, MQ * 256 / 4);
    wvt<<<(256 * 256 + 255) / 256, 256>>>(Wv, pWvT);
    wqt<<<(768 * 256 + 255) / 256, 256>>>(Wo, Wa, pWqT);
    bcat<<<3, 256>>>(bo, ba, pbq);

    // 1) value GEMM -> fp16 head-major   (119680 x 256 x 256)
    gemm_f16<true><<<dim3(2, MVAL / 128), 256>>>(pah, pWvT, bv, nullptr, pvalh, MVAL, 256);
    // 2) fused off|aw GEMM -> fp32        (20000 x 768 x 256)
    gemm_f16<false><<<dim3(6, (MQ + 127) / 128), 256>>>(pqh, pWqT, pbq, pqout, nullptr, MQ, 768);

    // 3) softmax + deformable sampling + aggregation
    msda_sample<<<(MQ * NHD) / 8, 256>>>(refpts, spatial, lsi, out);
}

// round 8
// speedup vs baseline: 3.3512x; 1.1200x over previous
#include <cuda_runtime.h>
#include <cuda_fp16.h>
#include <cstdint>

// ---------------------------------------------------------------------------
// Problem constants
// ---------------------------------------------------------------------------
#define NB      8
#define LQN     2500
#define NHD     8
#define NLV     4
#define NPT     8
#define NZP     4
#define LEN_IN  14960
#define MVAL    (NB * LEN_IN)   // 119680 = 935*128
#define MQ      (NB * LQN)      // 20000

// ---------------------------------------------------------------------------
// Scratch (static device globals)
// ---------------------------------------------------------------------------
__device__ __align__(256) __half g_WvT[256 * 256];             // [n][k] fp16
__device__ __align__(256) __half g_WqT[768 * 256];             // Wo|Wa fused, [n][k] fp16
__device__ __align__(256) float  g_bq[768];                    // bo|ba fused
__device__ __align__(256) __half g_valueh[(size_t)MVAL * 256]; // head-major (n,h,token,32)
__device__ __align__(256) float  g_qout[(size_t)MQ * 768];     // cols 0-511 off, 512-767 aw

// ---------------------------------------------------------------------------
// PTX helpers (baseline PTX only)
// ---------------------------------------------------------------------------
__device__ __forceinline__ uint32_t smem_u32(const void* p) {
    uint32_t a;
    asm("{ .reg .u64 t; cvta.to.shared.u64 t, %1; cvt.u32.u64 %0, t; }" : "=r"(a) : "l"(p));
    return a;
}
__device__ __forceinline__ void cp16(uint32_t dst, const void* src) {
    asm volatile("cp.async.cg.shared.global [%0], [%1], 16;"
                 :: "r"(dst), "l"(src) : "memory");
}
__device__ __forceinline__ void cp_commit() { asm volatile("cp.async.commit_group;" ::: "memory"); }
__device__ __forceinline__ void cp_wait1()  { asm volatile("cp.async.wait_group 1;" ::: "memory"); }
__device__ __forceinline__ void cp_wait0()  { asm volatile("cp.async.wait_group 0;" ::: "memory"); }

__device__ __forceinline__ void ldm_x4(uint32_t r[4], uint32_t addr) {
    asm volatile("ldmatrix.sync.aligned.m8n8.x4.shared.b16 {%0,%1,%2,%3}, [%4];"
                 : "=r"(r[0]), "=r"(r[1]), "=r"(r[2]), "=r"(r[3]) : "r"(addr));
}
__device__ __forceinline__ void mma16816(float c[4], const uint32_t a[4], const uint32_t b[2]) {
    asm volatile(
        "mma.sync.aligned.m16n8k16.row.col.f32.f16.f16.f32 "
        "{%0,%1,%2,%3}, {%4,%5,%6,%7}, {%8,%9}, {%0,%1,%2,%3};"
        : "+f"(c[0]), "+f"(c[1]), "+f"(c[2]), "+f"(c[3])
        : "r"(a[0]), "r"(a[1]), "r"(a[2]), "r"(a[3]), "r"(b[0]), "r"(b[1]));
}
__device__ __forceinline__ uint32_t pack2h(float x, float y) {
    __half2 h = __floats2half2_rn(x, y);
    return *(const uint32_t*)&h;
}

// ---------------------------------------------------------------------------
// Fused weight prep: WvT[n][k], WqT = (Wo|Wa)[n][k], bq = bo|ba
// ---------------------------------------------------------------------------
__global__ void prep_w(const float* __restrict__ Wv, const float* __restrict__ Wo,
                       const float* __restrict__ Wa, const float* __restrict__ bo,
                       const float* __restrict__ ba, __half* __restrict__ WvT,
                       __half* __restrict__ WqT, float* __restrict__ bq)
{
    int idx = blockIdx.x * blockDim.x + threadIdx.x;
    if (idx < 65536) {
        int n = idx >> 8, k = idx & 255;
        WvT[idx] = __float2half(Wv[k * 256 + n]);
    } else if (idx < 65536 + 196608) {
        int j = idx - 65536;
        int n = j >> 8, k = j & 255;
        WqT[j] = __float2half((n < 512) ? Wo[k * 512 + n] : Wa[k * 256 + (n - 512)]);
    } else if (idx < 65536 + 196608 + 768) {
        int t = idx - 65536 - 196608;
        bq[t] = (t < 512) ? bo[t] : ba[t - 512];
    }
}

// ---------------------------------------------------------------------------
// FP16 tensor-core GEMM with fused fp32->fp16 A conversion:
//   C[M,N] = fp16(A[M,256]) @ BT[N,256]^T + bias[N]
// A: fp32 in gmem, LDG->cvt->STS (register double-buffered).
// B: fp16 in gmem, cp.async double-buffered.
// CTA 128x128, BK=32, 8 warps (warp tile 32x64), ldmatrix fragments,
// 80-byte padded SMEM rows. VOUT=true: fp16 head-major value output.
// ---------------------------------------------------------------------------
#define ROWB 80                      // bytes per 32-half SMEM row
#define TILEB (128 * ROWB)           // 10240
#define BUFB  (2 * TILEB)            // A + B per stage

template<bool VOUT>
__global__ __launch_bounds__(256) void gemm_f16(
    const float* __restrict__ A, const __half* __restrict__ BT,
    const float* __restrict__ bias, float* __restrict__ Cf, __half* __restrict__ Ch,
    int M, int N)
{
    __shared__ __align__(16) unsigned char sm[2 * BUFB];
    const uint32_t smb = smem_u32(sm);

    const int tid = threadIdx.x;
    const int lane = tid & 31, wid = tid >> 5;
    const int gid = lane >> 2, tig = lane & 3;
    const int wm = (wid >> 1) * 32, wn = (wid & 1) * 64;
    const int br = blockIdx.y, bc = blockIdx.x;

    // loader: thread -> chunks (r0,k0) and (r0+64,k0); chunk = 8 elements
    const int r0 = tid >> 2, k0 = tid & 3;
    const int gr0 = br * 128 + r0, gr1 = gr0 + 64;
    const int gr0c = (gr0 < M) ? gr0 : (M - 1);
    const int gr1c = (gr1 < M) ? gr1 : (M - 1);
    const float* aP0 = A + (size_t)gr0c * 256 + k0 * 8;
    const float* aP1 = A + (size_t)gr1c * 256 + k0 * 8;
    const __half* bP0 = BT + (size_t)(bc * 128 + r0) * 256 + k0 * 8;
    const __half* bP1 = BT + (size_t)(bc * 128 + r0 + 64) * 256 + k0 * 8;
    const uint32_t offA0 = r0 * ROWB + k0 * 16;
    const uint32_t offA1 = (r0 + 64) * ROWB + k0 * 16;

    float c[2][8][4];
    #pragma unroll
    for (int mi = 0; mi < 2; mi++)
        #pragma unroll
        for (int nj = 0; nj < 8; nj++)
            #pragma unroll
            for (int q = 0; q < 4; q++) c[mi][nj][q] = 0.f;

    float ar[2][8];   // A stage registers (fp32)

    auto ldgA = [&](int kt) {
        #pragma unroll
        for (int cch = 0; cch < 2; cch++) {
            const float* src = (cch ? aP1 : aP0) + kt * 32;
            float4 v0 = *(const float4*)src;
            float4 v1 = *(const float4*)(src + 4);
            ar[cch][0] = v0.x; ar[cch][1] = v0.y; ar[cch][2] = v0.z; ar[cch][3] = v0.w;
            ar[cch][4] = v1.x; ar[cch][5] = v1.y; ar[cch][6] = v1.z; ar[cch][7] = v1.w;
        }
    };
    auto stsA = [&](int buf) {
        unsigned char* base = sm + buf * BUFB;
        #pragma unroll
        for (int cch = 0; cch < 2; cch++) {
            uint4 u;
            u.x = pack2h(ar[cch][0], ar[cch][1]);
            u.y = pack2h(ar[cch][2], ar[cch][3]);
            u.z = pack2h(ar[cch][4], ar[cch][5]);
            u.w = pack2h(ar[cch][6], ar[cch][7]);
            *(uint4*)(base + (cch ? offA1 : offA0)) = u;
        }
    };
    auto bcp = [&](int kt, int buf) {
        const uint32_t bs = smb + buf * BUFB + TILEB;
        cp16(bs + offA0, bP0 + kt * 32);
        cp16(bs + offA1, bP1 + kt * 32);
        cp_commit();
    };

    // prologue
    ldgA(0); stsA(0); bcp(0, 0);
    ldgA(1);

    #pragma unroll 1
    for (int kt = 0; kt < 8; kt++) {
        const int cur = kt & 1, nxt = cur ^ 1;
        if (kt < 7) { stsA(nxt); bcp(kt + 1, nxt); }
        if (kt < 6) { ldgA(kt + 2); }
        if (kt < 7) cp_wait1(); else cp_wait0();
        __syncthreads();

        const uint32_t asB = smb + cur * BUFB;
        const uint32_t bsB = asB + TILEB;

        #pragma unroll
        for (int ks = 0; ks < 32; ks += 16) {
            const int kc0 = ks >> 3;
            uint32_t a[2][4], b[8][2];
            #pragma unroll
            for (int mi = 0; mi < 2; mi++) {
                const int row = wm + mi * 16 + (lane & 15);
                ldm_x4(a[mi], asB + row * ROWB + (kc0 + (lane >> 4)) * 16);
            }
            #pragma unroll
            for (int njp = 0; njp < 4; njp++) {
                const int row = wn + njp * 16 + ((lane >> 4) << 3) + (lane & 7);
                uint32_t t[4];
                ldm_x4(t, bsB + row * ROWB + (kc0 + ((lane >> 3) & 1)) * 16);
                b[2 * njp][0] = t[0]; b[2 * njp][1] = t[1];
                b[2 * njp + 1][0] = t[2]; b[2 * njp + 1][1] = t[3];
            }
            #pragma unroll
            for (int mi = 0; mi < 2; mi++)
                #pragma unroll
                for (int nj = 0; nj < 8; nj++)
                    mma16816(c[mi][nj], a[mi], b[nj]);
        }
        __syncthreads();
    }

    // ---- epilogue ----
    #pragma unroll
    for (int mi = 0; mi < 2; mi++) {
        const int rbase = br * 128 + wm + mi * 16 + gid;
        #pragma unroll
        for (int hh = 0; hh < 2; hh++) {
            const int row = rbase + hh * 8;
            if (row >= M) continue;
            if (VOUT) {
                const int n = row / LEN_IN, tok = row - n * LEN_IN;
                #pragma unroll
                for (int nj = 0; nj < 8; nj++) {
                    const int col = bc * 128 + wn + nj * 8 + tig * 2;
                    const float2 bb = *(const float2*)(bias + col);
                    __half2 hv = __floats2half2_rn(c[mi][nj][2 * hh] + bb.x,
                                                   c[mi][nj][2 * hh + 1] + bb.y);
                    const int h = col >> 5, ch = col & 31;
                    *(__half2*)(Ch + (((size_t)(n * 8 + h) * LEN_IN + tok) * 32 + ch)) = hv;
                }
            } else {
                #pragma unroll
                for (int nj = 0; nj < 8; nj++) {
                    const int col = bc * 128 + wn + nj * 8 + tig * 2;
                    const float2 bb = *(const float2*)(bias + col);
                    float2 o = make_float2(c[mi][nj][2 * hh] + bb.x,
                                           c[mi][nj][2 * hh + 1] + bb.y);
                    *(float2*)(Cf + (size_t)row * N + col) = o;
                }
            }
        }
    }
}

// ---------------------------------------------------------------------------
// Fused softmax + deformable bilinear sampling + aggregation (fp16 value,
// head-major layout). One warp per (n,q,h).
// ---------------------------------------------------------------------------
__global__ __launch_bounds__(256) void msda_sample(
    const float* __restrict__ ref,       // (N, LQ, NZ, 2)
    const int*   __restrict__ spatial,   // (NL, 2)
    const int*   __restrict__ lsi,       // (NL,)
    float*       __restrict__ out)       // (N, LQ, 256)
{
    __shared__ int4 sdata[8][32][2];

    const int lane = threadIdx.x & 31;
    const int wid  = threadIdx.x >> 5;
    const int gw   = blockIdx.x * 8 + wid;
    const int h    = gw & 7;
    const int nq   = gw >> 3;

    // ---- phase 1: lane = point (l*8+p) ----
    {
        const int l = lane >> 3, p = lane & 7;
        const int hl = spatial[2 * l], wl = spatial[2 * l + 1];
        const int start = lsi[l];

        const float2 offv = *(const float2*)(g_qout + (size_t)nq * 768 + (h * 4 + l) * 16 + p * 2);
        const int z = p & 3;
        const float2 rp = *(const float2*)(ref + ((size_t)nq * NZP + z) * 2);
        const float x = (rp.x + offv.x / (float)wl) * (float)wl - 0.5f;
        const float y = (rp.y + offv.y / (float)hl) * (float)hl - 0.5f;
        const float x0f = floorf(x), y0f = floorf(y);
        const float fx = x - x0f, fy = y - y0f;
        const int x0 = (int)x0f, y0 = (int)y0f;

        // warp softmax
        float a = g_qout[(size_t)nq * 768 + 512 + h * 32 + lane];
        float m = a;
        #pragma unroll
        for (int s = 16; s; s >>= 1) m = fmaxf(m, __shfl_xor_sync(0xffffffffu, m, s));
        float e = __expf(a - m);
        float ssum = e;
        #pragma unroll
        for (int s = 16; s; s >>= 1) ssum += __shfl_xor_sync(0xffffffffu, ssum, s);
        const float awn = e / ssum;

        const int bx = min(max(x0, 0), wl - 2);
        const int u0 = bx - x0;
        const float wx0 = (u0 == 0) ? (1.f - fx) : ((u0 == 1) ? fx : 0.f);
        const float wx1 = (u0 + 1 == 0) ? (1.f - fx) : ((u0 + 1 == 1) ? fx : 0.f);

        #pragma unroll
        for (int ry = 0; ry < 2; ry++) {
            const int yi = y0 + ry;
            const bool vy = (yi >= 0) && (yi < hl);
            const int yc = min(max(yi, 0), hl - 1);
            const float wy = (ry ? fy : 1.f - fy) * (vy ? awn : 0.f);
            sdata[wid][lane][ry] = make_int4(start + yc * wl + bx,
                                             __float_as_int(wx0 * wy),
                                             __float_as_int(wx1 * wy), 0);
        }
    }
    __syncwarp();

    // ---- phase 2: lane = p1|ry|s|cg ----
    const int n  = nq / LQN;
    const int p1 = lane >> 4;
    const int ry = (lane >> 3) & 1;
    const int s  = (lane >> 2) & 1;
    const int cg = lane & 3;
    const __half* vplane = g_valueh + ((size_t)(n * 8 + h)) * LEN_IN * 32;

    float acc[8];
    #pragma unroll
    for (int i = 0; i < 8; i++) acc[i] = 0.f;

    #pragma unroll 4
    for (int j = 0; j < 16; j++) {
        const int pt = 2 * j + p1;
        const int4 sd = sdata[wid][pt][ry];
        const float w = __int_as_float(s ? sd.z : sd.y);
        const uint4 v = *((const uint4*)(vplane + ((size_t)(sd.x + s) << 5)) + cg);
        const float2 f0 = __half22float2(*(const __half2*)&v.x);
        const float2 f1 = __half22float2(*(const __half2*)&v.y);
        const float2 f2 = __half22float2(*(const __half2*)&v.z);
        const float2 f3 = __half22float2(*(const __half2*)&v.w);
        acc[0] += w * f0.x; acc[1] += w * f0.y;
        acc[2] += w * f1.x; acc[3] += w * f1.y;
        acc[4] += w * f2.x; acc[5] += w * f2.y;
        acc[6] += w * f3.x; acc[7] += w * f3.y;
    }

    #pragma unroll
    for (int st = 16; st >= 4; st >>= 1) {
        #pragma unroll
        for (int i = 0; i < 8; i++)
            acc[i] += __shfl_xor_sync(0xffffffffu, acc[i], st);
    }
    if (lane < 4) {
        float* base = out + (size_t)nq * 256 + h * 32 + lane * 8;
        *(float4*)base       = make_float4(acc[0], acc[1], acc[2], acc[3]);
        *(float4*)(base + 4) = make_float4(acc[4], acc[5], acc[6], acc[7]);
    }
}

// ---------------------------------------------------------------------------
// Launch
// ---------------------------------------------------------------------------
extern "C" void kernel_launch(void* const* d_in, const int* in_sizes, int n_in,
                              void* d_out, int out_size)
{
    const float* query   = (const float*)d_in[0];
    // d_in[1] = query_pos (unused by the reference forward)
    const float* refpts  = (const float*)d_in[2];
    const float* inflat  = (const float*)d_in[3];
    const int*   spatial = (const int*)d_in[4];
    const int*   lsi     = (const int*)d_in[5];
    const float* Wv      = (const float*)d_in[6];
    const float* bv      = (const float*)d_in[7];
    const float* Wo      = (const float*)d_in[8];
    const float* bo      = (const float*)d_in[9];
    const float* Wa      = (const float*)d_in[10];
    const float* ba      = (const float*)d_in[11];
    float*       out     = (float*)d_out;

    __half *pWvT, *pWqT, *pvalh;
    float *pbq, *pqout;
    cudaGetSymbolAddress((void**)&pWvT,  g_WvT);
    cudaGetSymbolAddress((void**)&pWqT,  g_WqT);
    cudaGetSymbolAddress((void**)&pbq,   g_bq);
    cudaGetSymbolAddress((void**)&pvalh, g_valueh);
    cudaGetSymbolAddress((void**)&pqout, g_qout);

    // 0) fused weight prep (transposes + bias concat)
    prep_w<<<(65536 + 196608 + 768 + 255) / 256, 256>>>(Wv, Wo, Wa, bo, ba, pWvT, pWqT, pbq);

    // 1) value GEMM (fused fp32->fp16 A) -> fp16 head-major  (119680 x 256 x 256)
    gemm_f16<true><<<dim3(2, MVAL / 128), 256>>>(inflat, pWvT, bv, nullptr, pvalh, MVAL, 256);
    // 2) fused off|aw GEMM -> fp32                            (20000 x 768 x 256)
    gemm_f16<false><<<dim3(6, (MQ + 127) / 128), 256>>>(query, pWqT, pbq, pqout, nullptr, MQ, 768);

    // 3) softmax + deformable sampling + aggregation
    msda_sample<<<(MQ * NHD) / 8, 256>>>(refpts, spatial, lsi, out);
}

// round 9
// speedup vs baseline: 3.5062x; 1.0462x over previous
#include <cuda_runtime.h>
#include <cuda_fp16.h>
#include <cstdint>

// ---------------------------------------------------------------------------
// Problem constants
// ---------------------------------------------------------------------------
#define NB      8
#define LQN     2500
#define NHD     8
#define NLV     4
#define NPT     8
#define NZP     4
#define LEN_IN  14960
#define MVAL    (NB * LEN_IN)   // 119680 = 935*128
#define MQ      (NB * LQN)      // 20000

// ---------------------------------------------------------------------------
// Scratch (static device globals)
// ---------------------------------------------------------------------------
__device__ __align__(256) __half g_WvT[256 * 256];             // [n][k] fp16
__device__ __align__(256) __half g_WqT[768 * 256];             // Wo|Wa fused, [n][k] fp16
__device__ __align__(256) float  g_bq[768];                    // bo|ba fused
__device__ __align__(256) __half g_valueh[(size_t)MVAL * 256]; // head-major (n,h,token,32)
__device__ __align__(256) float  g_qout[(size_t)MQ * 768];     // cols 0-511 off, 512-767 aw

// ---------------------------------------------------------------------------
// PTX helpers (baseline PTX only)
// ---------------------------------------------------------------------------
__device__ __forceinline__ uint32_t smem_u32(const void* p) {
    uint32_t a;
    asm("{ .reg .u64 t; cvta.to.shared.u64 t, %1; cvt.u32.u64 %0, t; }" : "=r"(a) : "l"(p));
    return a;
}
__device__ __forceinline__ void cp16(uint32_t dst, const void* src) {
    asm volatile("cp.async.cg.shared.global [%0], [%1], 16;"
                 :: "r"(dst), "l"(src) : "memory");
}
__device__ __forceinline__ void cp_commit() { asm volatile("cp.async.commit_group;" ::: "memory"); }
__device__ __forceinline__ void cp_wait1()  { asm volatile("cp.async.wait_group 1;" ::: "memory"); }
__device__ __forceinline__ void cp_wait0()  { asm volatile("cp.async.wait_group 0;" ::: "memory"); }

__device__ __forceinline__ void ldm_x4(uint32_t r[4], uint32_t addr) {
    asm volatile("ldmatrix.sync.aligned.m8n8.x4.shared.b16 {%0,%1,%2,%3}, [%4];"
                 : "=r"(r[0]), "=r"(r[1]), "=r"(r[2]), "=r"(r[3]) : "r"(addr));
}
__device__ __forceinline__ void mma16816(float c[4], const uint32_t a[4], const uint32_t b[2]) {
    asm volatile(
        "mma.sync.aligned.m16n8k16.row.col.f32.f16.f16.f32 "
        "{%0,%1,%2,%3}, {%4,%5,%6,%7}, {%8,%9}, {%0,%1,%2,%3};"
        : "+f"(c[0]), "+f"(c[1]), "+f"(c[2]), "+f"(c[3])
        : "r"(a[0]), "r"(a[1]), "r"(a[2]), "r"(a[3]), "r"(b[0]), "r"(b[1]));
}
__device__ __forceinline__ uint32_t pack2h(float x, float y) {
    __half2 h = __floats2half2_rn(x, y);
    return *(const uint32_t*)&h;
}

// ---------------------------------------------------------------------------
// Fused weight prep: WvT[n][k], WqT = (Wo|Wa)[n][k], bq = bo|ba
// ---------------------------------------------------------------------------
__global__ void prep_w(const float* __restrict__ Wv, const float* __restrict__ Wo,
                       const float* __restrict__ Wa, const float* __restrict__ bo,
                       const float* __restrict__ ba, __half* __restrict__ WvT,
                       __half* __restrict__ WqT, float* __restrict__ bq)
{
    int idx = blockIdx.x * blockDim.x + threadIdx.x;
    if (idx < 65536) {
        int n = idx >> 8, k = idx & 255;
        WvT[idx] = __float2half(Wv[k * 256 + n]);
    } else if (idx < 65536 + 196608) {
        int j = idx - 65536;
        int n = j >> 8, k = j & 255;
        WqT[j] = __float2half((n < 512) ? Wo[k * 512 + n] : Wa[k * 256 + (n - 512)]);
    } else if (idx < 65536 + 196608 + 768) {
        int t = idx - 65536 - 196608;
        bq[t] = (t < 512) ? bo[t] : ba[t - 512];
    }
}

// ---------------------------------------------------------------------------
// FP16 tensor-core GEMM with fused fp32->fp16 A conversion (as round 8):
//   C[M,N] = fp16(A[M,256]) @ BT[N,256]^T + bias[N]
// ---------------------------------------------------------------------------
#define ROWB 80                      // bytes per 32-half SMEM row
#define TILEB (128 * ROWB)           // 10240
#define BUFB  (2 * TILEB)            // A + B per stage

template<bool VOUT>
__global__ __launch_bounds__(256) void gemm_f16(
    const float* __restrict__ A, const __half* __restrict__ BT,
    const float* __restrict__ bias, float* __restrict__ Cf, __half* __restrict__ Ch,
    int M, int N)
{
    __shared__ __align__(16) unsigned char sm[2 * BUFB];
    const uint32_t smb = smem_u32(sm);

    const int tid = threadIdx.x;
    const int lane = tid & 31, wid = tid >> 5;
    const int gid = lane >> 2, tig = lane & 3;
    const int wm = (wid >> 1) * 32, wn = (wid & 1) * 64;
    const int br = blockIdx.y, bc = blockIdx.x;

    const int r0 = tid >> 2, k0 = tid & 3;
    const int gr0 = br * 128 + r0, gr1 = gr0 + 64;
    const int gr0c = (gr0 < M) ? gr0 : (M - 1);
    const int gr1c = (gr1 < M) ? gr1 : (M - 1);
    const float* aP0 = A + (size_t)gr0c * 256 + k0 * 8;
    const float* aP1 = A + (size_t)gr1c * 256 + k0 * 8;
    const __half* bP0 = BT + (size_t)(bc * 128 + r0) * 256 + k0 * 8;
    const __half* bP1 = BT + (size_t)(bc * 128 + r0 + 64) * 256 + k0 * 8;
    const uint32_t offA0 = r0 * ROWB + k0 * 16;
    const uint32_t offA1 = (r0 + 64) * ROWB + k0 * 16;

    float c[2][8][4];
    #pragma unroll
    for (int mi = 0; mi < 2; mi++)
        #pragma unroll
        for (int nj = 0; nj < 8; nj++)
            #pragma unroll
            for (int q = 0; q < 4; q++) c[mi][nj][q] = 0.f;

    float ar[2][8];

    auto ldgA = [&](int kt) {
        #pragma unroll
        for (int cch = 0; cch < 2; cch++) {
            const float* src = (cch ? aP1 : aP0) + kt * 32;
            float4 v0 = *(const float4*)src;
            float4 v1 = *(const float4*)(src + 4);
            ar[cch][0] = v0.x; ar[cch][1] = v0.y; ar[cch][2] = v0.z; ar[cch][3] = v0.w;
            ar[cch][4] = v1.x; ar[cch][5] = v1.y; ar[cch][6] = v1.z; ar[cch][7] = v1.w;
        }
    };
    auto stsA = [&](int buf) {
        unsigned char* base = sm + buf * BUFB;
        #pragma unroll
        for (int cch = 0; cch < 2; cch++) {
            uint4 u;
            u.x = pack2h(ar[cch][0], ar[cch][1]);
            u.y = pack2h(ar[cch][2], ar[cch][3]);
            u.z = pack2h(ar[cch][4], ar[cch][5]);
            u.w = pack2h(ar[cch][6], ar[cch][7]);
            *(uint4*)(base + (cch ? offA1 : offA0)) = u;
        }
    };
    auto bcp = [&](int kt, int buf) {
        const uint32_t bs = smb + buf * BUFB + TILEB;
        cp16(bs + offA0, bP0 + kt * 32);
        cp16(bs + offA1, bP1 + kt * 32);
        cp_commit();
    };

    ldgA(0); stsA(0); bcp(0, 0);
    ldgA(1);

    #pragma unroll 1
    for (int kt = 0; kt < 8; kt++) {
        const int cur = kt & 1, nxt = cur ^ 1;
        if (kt < 7) { stsA(nxt); bcp(kt + 1, nxt); }
        if (kt < 6) { ldgA(kt + 2); }
        if (kt < 7) cp_wait1(); else cp_wait0();
        __syncthreads();

        const uint32_t asB = smb + cur * BUFB;
        const uint32_t bsB = asB + TILEB;

        #pragma unroll
        for (int ks = 0; ks < 32; ks += 16) {
            const int kc0 = ks >> 3;
            uint32_t a[2][4], b[8][2];
            #pragma unroll
            for (int mi = 0; mi < 2; mi++) {
                const int row = wm + mi * 16 + (lane & 15);
                ldm_x4(a[mi], asB + row * ROWB + (kc0 + (lane >> 4)) * 16);
            }
            #pragma unroll
            for (int njp = 0; njp < 4; njp++) {
                const int row = wn + njp * 16 + ((lane >> 4) << 3) + (lane & 7);
                uint32_t t[4];
                ldm_x4(t, bsB + row * ROWB + (kc0 + ((lane >> 3) & 1)) * 16);
                b[2 * njp][0] = t[0]; b[2 * njp][1] = t[1];
                b[2 * njp + 1][0] = t[2]; b[2 * njp + 1][1] = t[3];
            }
            #pragma unroll
            for (int mi = 0; mi < 2; mi++)
                #pragma unroll
                for (int nj = 0; nj < 8; nj++)
                    mma16816(c[mi][nj], a[mi], b[nj]);
        }
        __syncthreads();
    }

    #pragma unroll
    for (int mi = 0; mi < 2; mi++) {
        const int rbase = br * 128 + wm + mi * 16 + gid;
        #pragma unroll
        for (int hh = 0; hh < 2; hh++) {
            const int row = rbase + hh * 8;
            if (row >= M) continue;
            if (VOUT) {
                const int n = row / LEN_IN, tok = row - n * LEN_IN;
                #pragma unroll
                for (int nj = 0; nj < 8; nj++) {
                    const int col = bc * 128 + wn + nj * 8 + tig * 2;
                    const float2 bb = *(const float2*)(bias + col);
                    __half2 hv = __floats2half2_rn(c[mi][nj][2 * hh] + bb.x,
                                                   c[mi][nj][2 * hh + 1] + bb.y);
                    const int h = col >> 5, ch = col & 31;
                    *(__half2*)(Ch + (((size_t)(n * 8 + h) * LEN_IN + tok) * 32 + ch)) = hv;
                }
            } else {
                #pragma unroll
                for (int nj = 0; nj < 8; nj++) {
                    const int col = bc * 128 + wn + nj * 8 + tig * 2;
                    const float2 bb = *(const float2*)(bias + col);
                    float2 o = make_float2(c[mi][nj][2 * hh] + bb.x,
                                           c[mi][nj][2 * hh + 1] + bb.y);
                    *(float2*)(Cf + (size_t)row * N + col) = o;
                }
            }
        }
    }
}

// ---------------------------------------------------------------------------
// Fused softmax + deformable bilinear sampling + aggregation.
// One warp per (n,q,h).
// Phase 1 (lane = point): softmax + tap prep -> sdata[point][row] =
//   int2{ byte offset of 2-slot span, half2{w_slot0, w_slot1} } (weights
//   include awn, row validity and clamping).
// Phase 2 (lane = p2|ry|cg): 4 points/iter-pair; per (point,row) a lane loads
//   both col-slots (2x LDG.128, contiguous 128 B), accumulates 4 taps in fp16
//   (HMUL2/HFMA2), converts to fp32 every 4 taps, shfl-reduces over
//   (p2, ry) at the end. Cuts issue count ~40% vs per-tap fp32 path.
// ---------------------------------------------------------------------------
__global__ __launch_bounds__(256) void msda_sample(
    const float* __restrict__ ref,       // (N, LQ, NZ, 2)
    const int*   __restrict__ spatial,   // (NL, 2)
    const int*   __restrict__ lsi,       // (NL,)
    float*       __restrict__ out)       // (N, LQ, 256)
{
    __shared__ int2 sdata[8][32][2];     // [warp][point][ry] = {byte_off, w01_h2}

    const int lane = threadIdx.x & 31;
    const int wid  = threadIdx.x >> 5;
    const int gw   = blockIdx.x * 8 + wid;
    const int h    = gw & 7;
    const int nq   = gw >> 3;

    // ---- phase 1: lane = point (l*8+p) ----
    {
        const int l = lane >> 3, p = lane & 7;
        const int hl = spatial[2 * l], wl = spatial[2 * l + 1];
        const int start = lsi[l];

        const float2 offv = *(const float2*)(g_qout + (size_t)nq * 768 + (h * 4 + l) * 16 + p * 2);
        const int z = p & 3;
        const float2 rp = *(const float2*)(ref + ((size_t)nq * NZP + z) * 2);
        const float x = (rp.x + offv.x / (float)wl) * (float)wl - 0.5f;
        const float y = (rp.y + offv.y / (float)hl) * (float)hl - 0.5f;
        const float x0f = floorf(x), y0f = floorf(y);
        const float fx = x - x0f, fy = y - y0f;
        const int x0 = (int)x0f, y0 = (int)y0f;

        // warp softmax over the 32 logits
        float a = g_qout[(size_t)nq * 768 + 512 + h * 32 + lane];
        float m = a;
        #pragma unroll
        for (int s = 16; s; s >>= 1) m = fmaxf(m, __shfl_xor_sync(0xffffffffu, m, s));
        float e = __expf(a - m);
        float ssum = e;
        #pragma unroll
        for (int s = 16; s; s >>= 1) ssum += __shfl_xor_sync(0xffffffffu, ssum, s);
        const float awn = e / ssum;

        const int bx = min(max(x0, 0), wl - 2);
        const int u0 = bx - x0;
        const float wx0 = (u0 == 0) ? (1.f - fx) : ((u0 == 1) ? fx : 0.f);
        const float wx1 = (u0 + 1 == 0) ? (1.f - fx) : ((u0 + 1 == 1) ? fx : 0.f);

        #pragma unroll
        for (int ry = 0; ry < 2; ry++) {
            const int yi = y0 + ry;
            const bool vy = (yi >= 0) && (yi < hl);
            const int yc = min(max(yi, 0), hl - 1);
            const float wy = (ry ? fy : 1.f - fy) * (vy ? awn : 0.f);
            sdata[wid][lane][ry] = make_int2((start + yc * wl + bx) * 64,
                                            (int)pack2h(wx0 * wy, wx1 * wy));
        }
    }
    __syncwarp();

    // ---- phase 2: lane = p2 (lane>>3, 4 points/iter) | ry | cg (8B chunk) ----
    const int n  = nq / LQN;
    const int p2 = lane >> 3;            // 0..3
    const int ry = (lane >> 2) & 1;      // row slot
    const int cg = lane & 3;             // 16B channel chunk
    const char* vbytes = (const char*)g_valueh
                       + ((size_t)(n * 8 + h)) * (LEN_IN * 64) + cg * 16;

    float acc[8];
    #pragma unroll
    for (int i = 0; i < 8; i++) acc[i] = 0.f;

    #pragma unroll
    for (int j2 = 0; j2 < 4; j2++) {
        __half2 hacc[4];
        #pragma unroll
        for (int jj = 0; jj < 2; jj++) {
            const int pt = (2 * j2 + jj) * 4 + p2;
            const int2 sd = sdata[wid][pt][ry];
            const __half2 wp = *(const __half2*)&sd.y;
            const __half2 w0 = __half2half2(__low2half(wp));
            const __half2 w1 = __half2half2(__high2half(wp));
            const char* b = vbytes + (uint32_t)sd.x;
            const uint4 v0 = *(const uint4*)b;
            const uint4 v1 = *(const uint4*)(b + 64);
            if (jj == 0) {
                hacc[0] = __hmul2(*(const __half2*)&v0.x, w0);
                hacc[1] = __hmul2(*(const __half2*)&v0.y, w0);
                hacc[2] = __hmul2(*(const __half2*)&v0.z, w0);
                hacc[3] = __hmul2(*(const __half2*)&v0.w, w0);
            } else {
                hacc[0] = __hfma2(*(const __half2*)&v0.x, w0, hacc[0]);
                hacc[1] = __hfma2(*(const __half2*)&v0.y, w0, hacc[1]);
                hacc[2] = __hfma2(*(const __half2*)&v0.z, w0, hacc[2]);
                hacc[3] = __hfma2(*(const __half2*)&v0.w, w0, hacc[3]);
            }
            hacc[0] = __hfma2(*(const __half2*)&v1.x, w1, hacc[0]);
            hacc[1] = __hfma2(*(const __half2*)&v1.y, w1, hacc[1]);
            hacc[2] = __hfma2(*(const __half2*)&v1.z, w1, hacc[2]);
            hacc[3] = __hfma2(*(const __half2*)&v1.w, w1, hacc[3]);
        }
        #pragma unroll
        for (int i = 0; i < 4; i++) {
            const float2 f = __half22float2(hacc[i]);
            acc[2 * i]     += f.x;
            acc[2 * i + 1] += f.y;
        }
    }

    // reduce over ry (bit 2) and p2 (bits 3-4)
    #pragma unroll
    for (int st = 16; st >= 4; st >>= 1) {
        #pragma unroll
        for (int i = 0; i < 8; i++)
            acc[i] += __shfl_xor_sync(0xffffffffu, acc[i], st);
    }
    if (lane < 4) {
        float* base = out + (size_t)nq * 256 + h * 32 + lane * 8;
        *(float4*)base       = make_float4(acc[0], acc[1], acc[2], acc[3]);
        *(float4*)(base + 4) = make_float4(acc[4], acc[5], acc[6], acc[7]);
    }
}

// ---------------------------------------------------------------------------
// Launch
// ---------------------------------------------------------------------------
extern "C" void kernel_launch(void* const* d_in, const int* in_sizes, int n_in,
                              void* d_out, int out_size)
{
    const float* query   = (const float*)d_in[0];
    // d_in[1] = query_pos (unused by the reference forward)
    const float* refpts  = (const float*)d_in[2];
    const float* inflat  = (const float*)d_in[3];
    const int*   spatial = (const int*)d_in[4];
    const int*   lsi     = (const int*)d_in[5];
    const float* Wv      = (const float*)d_in[6];
    const float* bv      = (const float*)d_in[7];
    const float* Wo      = (const float*)d_in[8];
    const float* bo      = (const float*)d_in[9];
    const float* Wa      = (const float*)d_in[10];
    const float* ba      = (const float*)d_in[11];
    float*       out     = (float*)d_out;

    __half *pWvT, *pWqT, *pvalh;
    float *pbq, *pqout;
    cudaGetSymbolAddress((void**)&pWvT,  g_WvT);
    cudaGetSymbolAddress((void**)&pWqT,  g_WqT);
    cudaGetSymbolAddress((void**)&pbq,   g_bq);
    cudaGetSymbolAddress((void**)&pvalh, g_valueh);
    cudaGetSymbolAddress((void**)&pqout, g_qout);

    // 0) fused weight prep
    prep_w<<<(65536 + 196608 + 768 + 255) / 256, 256>>>(Wv, Wo, Wa, bo, ba, pWvT, pWqT, pbq);

    // 1) value GEMM (fused fp32->fp16 A) -> fp16 head-major  (119680 x 256 x 256)
    gemm_f16<true><<<dim3(2, MVAL / 128), 256>>>(inflat, pWvT, bv, nullptr, pvalh, MVAL, 256);
    // 2) fused off|aw GEMM -> fp32                            (20000 x 768 x 256)
    gemm_f16<false><<<dim3(6, (MQ + 127) / 128), 256>>>(query, pWqT, pbq, pqout, nullptr, MQ, 768);

    // 3) softmax + deformable sampling + aggregation
    msda_sample<<<(MQ * NHD) / 8, 256>>>(refpts, spatial, lsi, out);
}

// round 12
// speedup vs baseline: 3.7644x; 1.0737x over previous
#include <cuda_runtime.h>
#include <cuda_fp16.h>
#include <cstdint>

// ---------------------------------------------------------------------------
// Problem constants
// ---------------------------------------------------------------------------
#define NB      8
#define LQN     2500
#define NHD     8
#define NLV     4
#define NPT     8
#define NZP     4
#define LEN_IN  14960
#define MVAL    (NB * LEN_IN)   // 119680 = 935*128
#define MQ      (NB * LQN)      // 20000

#define VAL_CTAS  (2 * (MVAL / 128))          // 1870
#define QOUT_CTAS (6 * ((MQ + 127) / 128))    // 942

// ---------------------------------------------------------------------------
// Scratch (static device globals)
// ---------------------------------------------------------------------------
__device__ __align__(256) __half g_WvT[256 * 256];             // [n][k] fp16
__device__ __align__(256) __half g_WqT[768 * 256];             // Wo|Wa fused, [n][k] fp16
__device__ __align__(256) float  g_bq[768];                    // bo|ba fused
__device__ __align__(256) __half g_valueh[(size_t)MVAL * 256]; // head-major (n,h,token,32)
__device__ __align__(256) float  g_qout[(size_t)MQ * 768];     // cols 0-511 off, 512-767 aw

// ---------------------------------------------------------------------------
// PTX helpers (baseline PTX only)
// ---------------------------------------------------------------------------
__device__ __forceinline__ uint32_t smem_u32(const void* p) {
    uint32_t a;
    asm("{ .reg .u64 t; cvta.to.shared.u64 t, %1; cvt.u32.u64 %0, t; }" : "=r"(a) : "l"(p));
    return a;
}
__device__ __forceinline__ void cp16(uint32_t dst, const void* src) {
    asm volatile("cp.async.cg.shared.global [%0], [%1], 16;"
                 :: "r"(dst), "l"(src) : "memory");
}
__device__ __forceinline__ void cp_commit() { asm volatile("cp.async.commit_group;" ::: "memory"); }
__device__ __forceinline__ void cp_wait1()  { asm volatile("cp.async.wait_group 1;" ::: "memory"); }
__device__ __forceinline__ void cp_wait0()  { asm volatile("cp.async.wait_group 0;" ::: "memory"); }

__device__ __forceinline__ void ldm_x4(uint32_t r[4], uint32_t addr) {
    asm volatile("ldmatrix.sync.aligned.m8n8.x4.shared.b16 {%0,%1,%2,%3}, [%4];"
                 : "=r"(r[0]), "=r"(r[1]), "=r"(r[2]), "=r"(r[3]) : "r"(addr));
}
__device__ __forceinline__ void mma16816(float c[4], const uint32_t a[4], const uint32_t b[2]) {
    asm volatile(
        "mma.sync.aligned.m16n8k16.row.col.f32.f16.f16.f32 "
        "{%0,%1,%2,%3}, {%4,%5,%6,%7}, {%8,%9}, {%0,%1,%2,%3};"
        : "+f"(c[0]), "+f"(c[1]), "+f"(c[2]), "+f"(c[3])
        : "r"(a[0]), "r"(a[1]), "r"(a[2]), "r"(a[3]), "r"(b[0]), "r"(b[1]));
}
__device__ __forceinline__ uint32_t pack2h(float x, float y) {
    __half2 h = __floats2half2_rn(x, y);
    return *(const uint32_t*)&h;
}

// ---------------------------------------------------------------------------
// Fused weight prep: WvT[n][k], WqT = (Wo|Wa)[n][k], bq = bo|ba
// ---------------------------------------------------------------------------
__global__ void prep_w(const float* __restrict__ Wv, const float* __restrict__ Wo,
                       const float* __restrict__ Wa, const float* __restrict__ bo,
                       const float* __restrict__ ba, __half* __restrict__ WvT,
                       __half* __restrict__ WqT, float* __restrict__ bq)
{
    int idx = blockIdx.x * blockDim.x + threadIdx.x;
    if (idx < 65536) {
        int n = idx >> 8, k = idx & 255;
        WvT[idx] = __float2half(Wv[k * 256 + n]);
    } else if (idx < 65536 + 196608) {
        int j = idx - 65536;
        int n = j >> 8, k = j & 255;
        WqT[j] = __float2half((n < 512) ? Wo[k * 512 + n] : Wa[k * 256 + (n - 512)]);
    } else if (idx < 65536 + 196608 + 768) {
        int t = idx - 65536 - 196608;
        bq[t] = (t < 512) ? bo[t] : ba[t - 512];
    }
}

// ---------------------------------------------------------------------------
// FP16 tensor-core GEMM body (fused fp32->fp16 A conversion):
//   C[.,N] tile (br,bc) of fp16(A[M,256]) @ BT[N,256]^T + bias[N]
// VOUT=true: fp16 head-major value output; else fp32 row-major.
// ---------------------------------------------------------------------------
#define ROWB 80                      // bytes per 32-half SMEM row
#define TILEB (128 * ROWB)           // 10240
#define BUFB  (2 * TILEB)            // A + B per stage

template<bool VOUT>
__device__ __forceinline__ void gemm_body(
    unsigned char* sm,
    const float* __restrict__ A, const __half* __restrict__ BT,
    const float* __restrict__ bias, float* __restrict__ Cf, __half* __restrict__ Ch,
    int M, int N, int bc, int br)
{
    const uint32_t smb = smem_u32(sm);
    const int tid = threadIdx.x;
    const int lane = tid & 31, wid = tid >> 5;
    const int gid = lane >> 2, tig = lane & 3;
    const int wm = (wid >> 1) * 32, wn = (wid & 1) * 64;

    const int r0 = tid >> 2, k0 = tid & 3;
    const int gr0 = br * 128 + r0, gr1 = gr0 + 64;
    const int gr0c = (gr0 < M) ? gr0 : (M - 1);
    const int gr1c = (gr1 < M) ? gr1 : (M - 1);
    const float* aP0 = A + (size_t)gr0c * 256 + k0 * 8;
    const float* aP1 = A + (size_t)gr1c * 256 + k0 * 8;
    const __half* bP0 = BT + (size_t)(bc * 128 + r0) * 256 + k0 * 8;
    const __half* bP1 = BT + (size_t)(bc * 128 + r0 + 64) * 256 + k0 * 8;
    const uint32_t offA0 = r0 * ROWB + k0 * 16;
    const uint32_t offA1 = (r0 + 64) * ROWB + k0 * 16;

    float c[2][8][4];
    #pragma unroll
    for (int mi = 0; mi < 2; mi++)
        #pragma unroll
        for (int nj = 0; nj < 8; nj++)
            #pragma unroll
            for (int q = 0; q < 4; q++) c[mi][nj][q] = 0.f;

    float ar[2][8];

    auto ldgA = [&](int kt) {
        #pragma unroll
        for (int cch = 0; cch < 2; cch++) {
            const float* src = (cch ? aP1 : aP0) + kt * 32;
            float4 v0 = *(const float4*)src;
            float4 v1 = *(const float4*)(src + 4);
            ar[cch][0] = v0.x; ar[cch][1] = v0.y; ar[cch][2] = v0.z; ar[cch][3] = v0.w;
            ar[cch][4] = v1.x; ar[cch][5] = v1.y; ar[cch][6] = v1.z; ar[cch][7] = v1.w;
        }
    };
    auto stsA = [&](int buf) {
        unsigned char* base = sm + buf * BUFB;
        #pragma unroll
        for (int cch = 0; cch < 2; cch++) {
            uint4 u;
            u.x = pack2h(ar[cch][0], ar[cch][1]);
            u.y = pack2h(ar[cch][2], ar[cch][3]);
            u.z = pack2h(ar[cch][4], ar[cch][5]);
            u.w = pack2h(ar[cch][6], ar[cch][7]);
            *(uint4*)(base + (cch ? offA1 : offA0)) = u;
        }
    };
    auto bcp = [&](int kt, int buf) {
        const uint32_t bs = smb + buf * BUFB + TILEB;
        cp16(bs + offA0, bP0 + kt * 32);
        cp16(bs + offA1, bP1 + kt * 32);
        cp_commit();
    };

    ldgA(0); stsA(0); bcp(0, 0);
    ldgA(1);

    #pragma unroll 1
    for (int kt = 0; kt < 8; kt++) {
        const int cur = kt & 1, nxt = cur ^ 1;
        if (kt < 7) { stsA(nxt); bcp(kt + 1, nxt); }
        if (kt < 6) { ldgA(kt + 2); }
        if (kt < 7) cp_wait1(); else cp_wait0();
        __syncthreads();

        const uint32_t asB = smb + cur * BUFB;
        const uint32_t bsB = asB + TILEB;

        #pragma unroll
        for (int ks = 0; ks < 32; ks += 16) {
            const int kc0 = ks >> 3;
            uint32_t a[2][4], b[8][2];
            #pragma unroll
            for (int mi = 0; mi < 2; mi++) {
                const int row = wm + mi * 16 + (lane & 15);
                ldm_x4(a[mi], asB + row * ROWB + (kc0 + (lane >> 4)) * 16);
            }
            #pragma unroll
            for (int njp = 0; njp < 4; njp++) {
                const int row = wn + njp * 16 + ((lane >> 4) << 3) + (lane & 7);
                uint32_t t[4];
                ldm_x4(t, bsB + row * ROWB + (kc0 + ((lane >> 3) & 1)) * 16);
                b[2 * njp][0] = t[0]; b[2 * njp][1] = t[1];
                b[2 * njp + 1][0] = t[2]; b[2 * njp + 1][1] = t[3];
            }
            #pragma unroll
            for (int mi = 0; mi < 2; mi++)
                #pragma unroll
                for (int nj = 0; nj < 8; nj++)
                    mma16816(c[mi][nj], a[mi], b[nj]);
        }
        __syncthreads();
    }

    #pragma unroll
    for (int mi = 0; mi < 2; mi++) {
        const int rbase = br * 128 + wm + mi * 16 + gid;
        #pragma unroll
        for (int hh = 0; hh < 2; hh++) {
            const int row = rbase + hh * 8;
            if (row >= M) continue;
            if (VOUT) {
                const int n = row / LEN_IN, tok = row - n * LEN_IN;
                #pragma unroll
                for (int nj = 0; nj < 8; nj++) {
                    const int col = bc * 128 + wn + nj * 8 + tig * 2;
                    const float2 bb = *(const float2*)(bias + col);
                    __half2 hv = __floats2half2_rn(c[mi][nj][2 * hh] + bb.x,
                                                   c[mi][nj][2 * hh + 1] + bb.y);
                    const int h = col >> 5, ch = col & 31;
                    *(__half2*)(Ch + (((size_t)(n * 8 + h) * LEN_IN + tok) * 32 + ch)) = hv;
                }
            } else {
                #pragma unroll
                for (int nj = 0; nj < 8; nj++) {
                    const int col = bc * 128 + wn + nj * 8 + tig * 2;
                    const float2 bb = *(const float2*)(bias + col);
                    float2 o = make_float2(c[mi][nj][2 * hh] + bb.x,
                                           c[mi][nj][2 * hh + 1] + bb.y);
                    *(float2*)(Cf + (size_t)row * N + col) = o;
                }
            }
        }
    }
}

// Merged launch: first VAL_CTAS blocks do the value GEMM, the rest do off|aw.
__global__ __launch_bounds__(256) void gemm_both(
    const float* __restrict__ inflat, const __half* __restrict__ WvT,
    const float* __restrict__ bv, __half* __restrict__ valh,
    const float* __restrict__ query, const __half* __restrict__ WqT,
    const float* __restrict__ bq, float* __restrict__ qout)
{
    __shared__ __align__(16) unsigned char sm[2 * BUFB];
    const int cta = blockIdx.x;
    if (cta < VAL_CTAS) {
        gemm_body<true>(sm, inflat, WvT, bv, nullptr, valh,
                        MVAL, 256, cta & 1, cta >> 1);
    } else {
        const int c2 = cta - VAL_CTAS;
        gemm_body<false>(sm, query, WqT, bq, qout, nullptr,
                         MQ, 768, c2 % 6, c2 / 6);
    }
}

// ---------------------------------------------------------------------------
// Fused softmax + deformable bilinear sampling + aggregation.
// One warp per (n,q,h).
// Phase 1 (lane = point): softmax + tap prep -> sdata[point][row] =
//   int2{ byte offset of 128B 2-token span, half2{w_slot0, w_slot1} }.
// Phase 2 (lane = p3|c): per iteration (point-group g, row r) one LDG.128
//   covers 4 full spans (8 lanes x 16B per span) -- minimal L1 line-touches.
//   Slot weight selected with one byte_perm; 2-tap fp16 chains, fp32 flush
//   per point-group; shfl-xor reduction over (s, p3).
// ---------------------------------------------------------------------------
__global__ __launch_bounds__(256) void msda_sample(
    const float* __restrict__ ref,       // (N, LQ, NZ, 2)
    const int*   __restrict__ spatial,   // (NL, 2)
    const int*   __restrict__ lsi,       // (NL,)
    float*       __restrict__ out)       // (N, LQ, 256)
{
    __shared__ int2 sdata[8][32][2];     // [warp][point][ry] = {byte_off, w01_h2}

    const int lane = threadIdx.x & 31;
    const int wid  = threadIdx.x >> 5;
    const int gw   = blockIdx.x * 8 + wid;
    const int h    = gw & 7;
    const int nq   = gw >> 3;

    // ---- phase 1: lane = point (l*8+p) ----
    {
        const int l = lane >> 3, p = lane & 7;
        const int hl = spatial[2 * l], wl = spatial[2 * l + 1];
        const int start = lsi[l];

        const float2 offv = *(const float2*)(g_qout + (size_t)nq * 768 + (h * 4 + l) * 16 + p * 2);
        const int z = p & 3;
        const float2 rp = *(const float2*)(ref + ((size_t)nq * NZP + z) * 2);
        const float x = (rp.x + offv.x / (float)wl) * (float)wl - 0.5f;
        const float y = (rp.y + offv.y / (float)hl) * (float)hl - 0.5f;
        const float x0f = floorf(x), y0f = floorf(y);
        const float fx = x - x0f, fy = y - y0f;
        const int x0 = (int)x0f, y0 = (int)y0f;

        // warp softmax over the 32 logits
        float a = g_qout[(size_t)nq * 768 + 512 + h * 32 + lane];
        float m = a;
        #pragma unroll
        for (int s = 16; s; s >>= 1) m = fmaxf(m, __shfl_xor_sync(0xffffffffu, m, s));
        float e = __expf(a - m);
        float ssum = e;
        #pragma unroll
        for (int s = 16; s; s >>= 1) ssum += __shfl_xor_sync(0xffffffffu, ssum, s);
        const float awn = e / ssum;

        const int bx = min(max(x0, 0), wl - 2);
        const int u0 = bx - x0;
        const float wx0 = (u0 == 0) ? (1.f - fx) : ((u0 == 1) ? fx : 0.f);
        const float wx1 = (u0 + 1 == 0) ? (1.f - fx) : ((u0 + 1 == 1) ? fx : 0.f);

        #pragma unroll
        for (int ry = 0; ry < 2; ry++) {
            const int yi = y0 + ry;
            const bool vy = (yi >= 0) && (yi < hl);
            const int yc = min(max(yi, 0), hl - 1);
            const float wy = (ry ? fy : 1.f - fy) * (vy ? awn : 0.f);
            sdata[wid][lane][ry] = make_int2((start + yc * wl + bx) * 64,
                                            (int)pack2h(wx0 * wy, wx1 * wy));
        }
    }
    __syncwarp();

    // ---- phase 2: lane = p3 (lane>>3) | c (lane&7: 16B chunk of 128B span) ----
    const int n  = nq / LQN;
    const int p3 = lane >> 3;              // point within group of 4
    const int c  = lane & 7;               // chunk within 2-token span
    const uint32_t wsel = (c & 4) ? 0x3232u : 0x1010u;  // replicate hi/lo half
    const char* vbytes = (const char*)g_valueh
                       + ((size_t)(n * 8 + h)) * (LEN_IN * 64) + c * 16;

    float acc[8];
    #pragma unroll
    for (int i = 0; i < 8; i++) acc[i] = 0.f;

    #pragma unroll
    for (int g = 0; g < 8; g++) {
        __half2 hacc[4];
        #pragma unroll
        for (int r = 0; r < 2; r++) {
            const int2 sd = sdata[wid][g * 4 + p3][r];
            const uint32_t wb_u = __byte_perm((uint32_t)sd.y, 0u, wsel);
            const __half2 wb = *(const __half2*)&wb_u;
            const uint4 v = *(const uint4*)(vbytes + (uint32_t)sd.x);
            if (r == 0) {
                hacc[0] = __hmul2(*(const __half2*)&v.x, wb);
                hacc[1] = __hmul2(*(const __half2*)&v.y, wb);
                hacc[2] = __hmul2(*(const __half2*)&v.z, wb);
                hacc[3] = __hmul2(*(const __half2*)&v.w, wb);
            } else {
                hacc[0] = __hfma2(*(const __half2*)&v.x, wb, hacc[0]);
                hacc[1] = __hfma2(*(const __half2*)&v.y, wb, hacc[1]);
                hacc[2] = __hfma2(*(const __half2*)&v.z, wb, hacc[2]);
                hacc[3] = __hfma2(*(const __half2*)&v.w, wb, hacc[3]);
            }
        }
        #pragma unroll
        for (int i = 0; i < 4; i++) {
            const float2 f = __half22float2(hacc[i]);
            acc[2 * i]     += f.x;
            acc[2 * i + 1] += f.y;
        }
    }

    // reduce over s (bit 2) and p3 (bits 3-4); lanes 0-3 hold chunk lane&3
    #pragma unroll
    for (int st = 16; st >= 4; st >>= 1) {
        #pragma unroll
        for (int i = 0; i < 8; i++)
            acc[i] += __shfl_xor_sync(0xffffffffu, acc[i], st);
    }
    if (lane < 4) {
        float* base = out + (size_t)nq * 256 + h * 32 + lane * 8;
        *(float4*)base       = make_float4(acc[0], acc[1], acc[2], acc[3]);
        *(float4*)(base + 4) = make_float4(acc[4], acc[5], acc[6], acc[7]);
    }
}

// ---------------------------------------------------------------------------
// Launch
// ---------------------------------------------------------------------------
extern "C" void kernel_launch(void* const* d_in, const int* in_sizes, int n_in,
                              void* d_out, int out_size)
{
    const float* query   = (const float*)d_in[0];
    // d_in[1] = query_pos (unused by the reference forward)
    const float* refpts  = (const float*)d_in[2];
    const float* inflat  = (const float*)d_in[3];
    const int*   spatial = (const int*)d_in[4];
    const int*   lsi     = (const int*)d_in[5];
    const float* Wv      = (const float*)d_in[6];
    const float* bv      = (const float*)d_in[7];
    const float* Wo      = (const float*)d_in[8];
    const float* bo      = (const float*)d_in[9];
    const float* Wa      = (const float*)d_in[10];
    const float* ba      = (const float*)d_in[11];
    float*       out     = (float*)d_out;

    __half *pWvT, *pWqT, *pvalh;
    float *pbq, *pqout;
    cudaGetSymbolAddress((void**)&pWvT,  g_WvT);
    cudaGetSymbolAddress((void**)&pWqT,  g_WqT);
    cudaGetSymbolAddress((void**)&pbq,   g_bq);
    cudaGetSymbolAddress((void**)&pvalh, g_valueh);
    cudaGetSymbolAddress((void**)&pqout, g_qout);

    // 0) fused weight prep
    prep_w<<<(65536 + 196608 + 768 + 255) / 256, 256>>>(Wv, Wo, Wa, bo, ba, pWvT, pWqT, pbq);

    // 1+2) merged GEMMs: value (fp16 head-major) + off|aw (fp32)
    gemm_both<<<VAL_CTAS + QOUT_CTAS, 256>>>(inflat, pWvT, bv, pvalh,
                                             query, pWqT, pbq, pqout);

    // 3) softmax + deformable sampling + aggregation
    msda_sample<<<(MQ * NHD) / 8, 256>>>(refpts, spatial, lsi, out);
}